// round 13
// baseline (speedup 1.0000x reference)
#include <cuda_runtime.h>
#include <cuda_bf16.h>
#include <cuda_fp16.h>
#include <math.h>
#include <stdint.h>

#define B_ 16
#define N_ 196
#define C_ 512
#define T_ 20
#define D_ 128
#define S_ 38
#define NP_ 224                    // padded row/col stride for chain matrices
#define MP2_ (NP_*NP_)             // 50176 elems per padded matrix
#define M_ 62720                   // B*N*T rows of the head GEMM (=490*128)
#define QSIZE 8028160              // B*D*T*N
#define INV_TEMP (1.0f/0.07f)
#define EPS_ 1e-20f

// ---------------- scratch (static device globals; no allocation) ----------------
__device__ float g_qA[B_*T_*N_*D_];                                  // [b][t][n][d] fp32
__device__ __align__(256) __nv_bfloat16 g_qbf[B_*T_*N_*D_];          // bf16 copy of q
__device__ __align__(256) __half g_qp1[(size_t)M_*C_];               // pooled acts fp16
__device__ __align__(256) __half g_qp2[(size_t)M_*C_];               // pooled acts fp16 scaled-res
__device__ __align__(256) __half g_W1[C_*D_];                        // W fp16 [c][d]
__device__ __align__(256) __half g_W2[C_*D_];                        // W fp16 scaled-res
__device__ __align__(256) __nv_bfloat16 g_P [(size_t)B_*S_*MP2_ + 256];
__device__ __align__(256) __nv_bfloat16 g_b1[(size_t)B_*13*MP2_ + 256];
__device__ __align__(256) __nv_bfloat16 g_b2[(size_t)B_*5*MP2_ + 256];
__device__ float g_At[(size_t)B_*MP2_];                              // final product fp32
__device__ float g_partial[2*B_];

// ---------------- mma / ldmatrix / cp.async helpers -------------------------
__device__ __forceinline__ void cpa16(void* dst_smem, const void* src) {
  unsigned d = (unsigned)__cvta_generic_to_shared(dst_smem);
  asm volatile("cp.async.cg.shared.global [%0], [%1], 16;\n" :: "r"(d), "l"(src));
}
__device__ __forceinline__ unsigned smem_u32p(const void* p) {
  return (unsigned)__cvta_generic_to_shared(p);
}
__device__ __forceinline__ void ldsm4(unsigned addr, unsigned* r) {
  asm volatile("ldmatrix.sync.aligned.m8n8.x4.shared.b16 {%0,%1,%2,%3}, [%4];\n"
               : "=r"(r[0]), "=r"(r[1]), "=r"(r[2]), "=r"(r[3]) : "r"(addr));
}
__device__ __forceinline__ void ldsm4t(unsigned addr, unsigned* r) {
  asm volatile("ldmatrix.sync.aligned.m8n8.x4.trans.shared.b16 {%0,%1,%2,%3}, [%4];\n"
               : "=r"(r[0]), "=r"(r[1]), "=r"(r[2]), "=r"(r[3]) : "r"(addr));
}
__device__ __forceinline__ void mma_bf16(float* d, const unsigned* a,
                                         unsigned b0, unsigned b1) {
  asm volatile(
      "mma.sync.aligned.m16n8k16.row.col.f32.bf16.bf16.f32 "
      "{%0,%1,%2,%3}, {%4,%5,%6,%7}, {%8,%9}, {%0,%1,%2,%3};\n"
      : "+f"(d[0]), "+f"(d[1]), "+f"(d[2]), "+f"(d[3])
      : "r"(a[0]), "r"(a[1]), "r"(a[2]), "r"(a[3]), "r"(b0), "r"(b1));
}
__device__ __forceinline__ void mma_f16(float* d, const unsigned* a,
                                        unsigned b0, unsigned b1) {
  asm volatile(
      "mma.sync.aligned.m16n8k16.row.col.f32.f16.f16.f32 "
      "{%0,%1,%2,%3}, {%4,%5,%6,%7}, {%8,%9}, {%0,%1,%2,%3};\n"
      : "+f"(d[0]), "+f"(d[1]), "+f"(d[2]), "+f"(d[3])
      : "r"(a[0]), "r"(a[1]), "r"(a[2]), "r"(a[3]), "r"(b0), "r"(b1));
}
__device__ __forceinline__ int aphys(int c, int r) {
  return (c < 24) ? ((c & ~7) | ((c & 7) ^ (r & 7))) : c;
}

// =============================================================================
// Kernel P: spatial pool + fp16 2-plane split of pooled activations.
// A1 = fp16(x); A2 = fp16(x + 255*(x - A1))  (= AH + 256*AL).
// =============================================================================
#define SMEM_P_BYTES (C_*21*sizeof(float))

__global__ __launch_bounds__(256) void kP(const float* __restrict__ maps) {
  extern __shared__ float qp[];             // [c][t] stride 21
  const int bn = blockIdx.x, tid = threadIdx.x;
  const float4* src = reinterpret_cast<const float4*>(maps) + (size_t)bn * (C_*T_);
  for (int i = tid; i < C_*T_; i += 256) {
    float4 v = src[i];
    const int c = i / 20, t = i - c*20;
    qp[c*21 + t] = (v.x + v.y + v.z + v.w) * 0.25f;
  }
  __syncthreads();
  __half* A1 = g_qp1 + (size_t)bn*20*C_;
  __half* A2 = g_qp2 + (size_t)bn*20*C_;
  for (int i = tid; i < 20*C_; i += 256) {
    const int t = i >> 9, c = i & 511;
    const float x = qp[c*21 + t];
    const __half h = __float2half_rn(x);
    A1[t*C_ + c] = h;
    A2[t*C_ + c] = __float2half_rn(x + 255.0f*(x - __half2float(h)));
  }
}

// W split: W1/W2 fp16 planes ([c][d] layout, row-major in c)
__global__ void kW(const float* __restrict__ W) {
  const int i = blockIdx.x*256 + threadIdx.x;   // grid 256 x 256 = 65536
  const float x = W[i];
  const __half h = __float2half_rn(x);
  g_W1[i] = h;
  g_W2[i] = __float2half_rn(x + 255.0f*(x - __half2float(h)));
}

// =============================================================================
// Kernel G: head GEMM, fp16 2-pass scaled split on mma.sync.
// P1 = A1@W1, P2 = A2@W2; y = P1 + (P2-P1)/256. Fused bias + L2 norm.
// CTA 128m x 128n, 256 thr (8 warps = 4m x 2n). K chunk 32, double buffered.
// =============================================================================
#define GSTAGE 36864
#define SMEM_G_BYTES (2*GSTAGE)             // 73728

__global__ __launch_bounds__(256) void kG(const float* __restrict__ bias) {
  extern __shared__ char smg[];
  const int m0  = blockIdx.x * 128;
  const int tid = threadIdx.x;
  const int lane = tid & 31, w = tid >> 5;
  const int wm = w & 3, nh = w >> 2;
  const int g = lane >> 2, tig = lane & 3;
  const int tg1 = (lane >> 3) & 1, tg2 = (lane >> 4) & 1;

  const __half* Am1 = g_qp1 + (size_t)m0*C_;
  const __half* Am2 = g_qp2 + (size_t)m0*C_;

  float acc1[2][8][4], acc2[2][8][4];
#pragma unroll
  for (int mt = 0; mt < 2; ++mt)
#pragma unroll
    for (int nt = 0; nt < 8; ++nt)
#pragma unroll
      for (int j = 0; j < 4; ++j) { acc1[mt][nt][j] = 0.f; acc2[mt][nt][j] = 0.f; }

  auto fill = [&](int stg, int k0) {
    char* S = smg + stg*GSTAGE;
#pragma unroll
    for (int i = 0; i < 4; ++i) {          // A planes: 128 rows x 4 chunks x 2
      const int idx = tid + i*256;
      const int r = idx >> 3, z = idx & 7;
      const int pl = z >> 2, c = z & 3;
      cpa16(S + pl*10240 + r*80 + c*16,
            (pl ? Am2 : Am1) + (size_t)r*C_ + k0 + c*8);
    }
#pragma unroll
    for (int i = 0; i < 4; ++i) {          // B planes: 32 rows x 16 chunks x 2
      const int idx = tid + i*256;
      const int r = idx >> 5, z = idx & 31;
      const int pl = z >> 4, c = z & 15;
      const int ph = (c & 8) | ((c & 7) ^ (r & 7));
      cpa16(S + 20480 + pl*8192 + r*256 + ph*16,
            (pl ? g_W2 : g_W1) + (size_t)(k0 + r)*D_ + c*8);
    }
    asm volatile("cp.async.commit_group;\n" ::: "memory");
  };

  fill(0, 0);
  for (int s = 0; s < 16; ++s) {
    if (s + 1 < 16) {
      fill((s + 1) & 1, (s + 1)*32);
      asm volatile("cp.async.wait_group 1;\n" ::: "memory");
    } else {
      asm volatile("cp.async.wait_group 0;\n" ::: "memory");
    }
    __syncthreads();

    const char* S = smg + (s & 1)*GSTAGE;
    const unsigned sBase = smem_u32p(S);
    const int arow = wm*32 + (lane & 7) + tg1*8;

#pragma unroll
    for (int ks = 0; ks < 2; ++ks) {
      unsigned a1[2][4], a2[2][4];
#pragma unroll
      for (int mt = 0; mt < 2; ++mt) {
        const unsigned ar = sBase + (arow + mt*16)*80 + (ks*2 + tg2)*16;
        ldsm4(ar, a1[mt]);
        ldsm4(ar + 10240, a2[mt]);
      }
      const int brow = ks*16 + (lane & 7) + tg1*8;
#pragma unroll
      for (int jp = 0; jp < 4; ++jp) {
        const int c  = nh*8 + 2*jp + tg2;
        const int ph = (c & 8) | ((c & 7) ^ (brow & 7));
        const unsigned ba = sBase + 20480 + brow*256 + ph*16;
        unsigned b1[4], b2[4];
        ldsm4t(ba, b1);
        ldsm4t(ba + 8192, b2);
#pragma unroll
        for (int mt = 0; mt < 2; ++mt) {
          mma_f16(acc1[mt][2*jp    ], a1[mt], b1[0], b1[1]);
          mma_f16(acc1[mt][2*jp + 1], a1[mt], b1[2], b1[3]);
          mma_f16(acc2[mt][2*jp    ], a2[mt], b2[0], b2[1]);
          mma_f16(acc2[mt][2*jp + 1], a2[mt], b2[2], b2[3]);
        }
      }
    }
    __syncthreads();
  }

  // ---- fused epilogue: combine passes, +bias, row L2 norm, write q ----
  float* y       = (float*)smg;            // [128][129]
  float* partial = y + 128*129;            // [128][2]
  float* inorm   = partial + 256;          // [128]
  const float inv256 = 1.0f/256.0f;
#pragma unroll
  for (int mt = 0; mt < 2; ++mt) {
    const int row = wm*32 + mt*16 + g;
#pragma unroll
    for (int nt = 0; nt < 8; ++nt) {
      const int col = nh*64 + nt*8 + 2*tig;
      const float* p1 = acc1[mt][nt];
      const float* p2 = acc2[mt][nt];
      y[ row     *129 + col    ] = p1[0] + (p2[0] - p1[0])*inv256;
      y[ row     *129 + col + 1] = p1[1] + (p2[1] - p1[1])*inv256;
      y[(row + 8)*129 + col    ] = p1[2] + (p2[2] - p1[2])*inv256;
      y[(row + 8)*129 + col + 1] = p1[3] + (p2[3] - p1[3])*inv256;
    }
  }
  __syncthreads();
  {
    const int r = tid >> 1, hf = tid & 1;
    float ssum = 0.f;
#pragma unroll 8
    for (int d = hf*64; d < hf*64 + 64; ++d) {
      const float v = y[r*129 + d] + bias[d];
      y[r*129 + d] = v;
      ssum += v*v;
    }
    partial[r*2 + hf] = ssum;
  }
  __syncthreads();
  if (tid < 128)
    inorm[tid] = 1.0f / fmaxf(sqrtf(partial[tid*2] + partial[tid*2 + 1]), 1e-12f);
  __syncthreads();
  for (int i = tid; i < 128*128; i += 256) {
    const int rr = i >> 7, d = i & 127;
    const int m  = m0 + rr;
    const int bn = m / 20, t = m - bn*20;
    const int bq = bn / N_, n = bn - bq*N_;
    const float v = y[rr*129 + d] * inorm[rr];
    const size_t qi = ((size_t)(bq*T_ + t)*N_ + n)*D_ + d;
    g_qA[qi]  = v;
    g_qbf[qi] = __float2bfloat16_rn(v);
  }
}

// =============================================================================
// Kernel Q: transpose q to output layout (B, d, T, N). (unchanged)
// =============================================================================
#define SMEM_Q_BYTES (N_*129*sizeof(float))

__global__ __launch_bounds__(256) void kQ(float* __restrict__ qout) {
  extern __shared__ float sq[];            // [n][d] stride 129
  const int t = blockIdx.x, b = blockIdx.y, tid = threadIdx.x;
  const float* src = g_qA + ((size_t)(b*T_ + t)*N_)*D_;
  for (int i = tid; i < N_*D_; i += 256) {
    const int n = i >> 7, d = i & 127;
    sq[n*129 + d] = src[i];
  }
  __syncthreads();
  for (int i = tid; i < N_*D_; i += 256) {
    const int d = i / N_, n = i - d*N_;
    qout[((size_t)(b*D_ + d)*T_ + t)*N_ + n] = sq[n*129 + d];
  }
}

// =============================================================================
// Kernel B: affinity + palindrome softmax on tensor cores. (unchanged R8)
// =============================================================================
#define KB_A_OFF 0
#define KB_B_OFF 57344                      // 224 rows x 256 B
#define KB_SM_OFF 114688
#define KB_SSTR 232                         // Sm bf16 col stride
#define SMEM_B2_BYTES (KB_SM_OFF + 224*KB_SSTR*2)   // 218624

__global__ __launch_bounds__(448, 1) void kB() {
  extern __shared__ char smb[];
  __shared__ float rinvA[224], cinvA[224];

  const int t = blockIdx.x, b = blockIdx.y, tid = threadIdx.x;
  const int lane = tid & 31, w = tid >> 5;
  const int g = lane >> 2, tig = lane & 3;

  {
    float4 z = make_float4(0.f, 0.f, 0.f, 0.f);
    ((float4*)(smb + KB_A_OFF + 196*256))[tid] = z;
    ((float4*)(smb + KB_B_OFF + 196*256))[tid] = z;
  }
  const __nv_bfloat16* Qa = g_qbf + ((size_t)(b*T_ + t    )*N_)*D_;
  const __nv_bfloat16* Qb = g_qbf + ((size_t)(b*T_ + t + 1)*N_)*D_;
  for (int idx = tid; idx < 196*16; idx += 448) {
    const int r = idx >> 4, c = idx & 15;
    const int ph = ((c & 7) ^ (r & 7)) | (c & 8);
    cpa16(smb + KB_A_OFF + r*256 + ph*16, Qa + (size_t)r*D_ + c*8);
    cpa16(smb + KB_B_OFF + r*256 + ph*16, Qb + (size_t)r*D_ + c*8);
  }
  asm volatile("cp.async.commit_group;\n" ::: "memory");
  asm volatile("cp.async.wait_group 0;\n" ::: "memory");
  __syncthreads();

  unsigned aF[8][4];
  {
    const int r = w*16 + (lane & 7) + ((lane >> 3) & 1)*8;
#pragma unroll
    for (int ks = 0; ks < 8; ++ks) {
      const int c  = 2*ks + ((lane >> 4) & 1);
      const int ph = ((c & 7) ^ (r & 7)) | (c & 8);
      ldsm4(smem_u32p(smb + KB_A_OFF) + r*256 + ph*16, aF[ks]);
    }
  }

  const unsigned bBase = smem_u32p(smb + KB_B_OFF);
  __nv_bfloat16* Sm = (__nv_bfloat16*)(smb + KB_SM_OFF);
  const int m0r = w*16 + g;
  float rsum0 = 0.f, rsum1 = 0.f;

  const int brlo = (lane & 7) + ((lane >> 4) & 1)*8;
  const int bchi = (lane >> 3) & 1;

  for (int ch = 0; ch < 7; ++ch) {
    float acc[4][4];
#pragma unroll
    for (int nt = 0; nt < 4; ++nt)
#pragma unroll
      for (int j = 0; j < 4; ++j) acc[nt][j] = 0.f;

#pragma unroll
    for (int ks = 0; ks < 8; ++ks) {
#pragma unroll
      for (int half = 0; half < 2; ++half) {
        const int r  = ch*32 + half*16 + brlo;
        const int c  = 2*ks + bchi;
        const int ph = ((c & 7) ^ (r & 7)) | (c & 8);
        unsigned bf[4];
        ldsm4(bBase + r*256 + ph*16, bf);
        mma_bf16(acc[half*2    ], aF[ks], bf[0], bf[1]);
        mma_bf16(acc[half*2 + 1], aF[ks], bf[2], bf[3]);
      }
    }
#pragma unroll
    for (int nt = 0; nt < 4; ++nt) {
      const int col = ch*32 + nt*8 + 2*tig;
      const float e0 = __expf(acc[nt][0]*INV_TEMP);
      const float e1 = __expf(acc[nt][1]*INV_TEMP);
      const float e2 = __expf(acc[nt][2]*INV_TEMP);
      const float e3 = __expf(acc[nt][3]*INV_TEMP);
      if (col     < N_) { rsum0 += e0; rsum1 += e2; }
      if (col + 1 < N_) { rsum0 += e1; rsum1 += e3; }
      *(__nv_bfloat162*)(Sm + (size_t)m0r*KB_SSTR + col) =
          __nv_bfloat162(__float2bfloat16_rn(e0), __float2bfloat16_rn(e1));
      *(__nv_bfloat162*)(Sm + (size_t)(m0r + 8)*KB_SSTR + col) =
          __nv_bfloat162(__float2bfloat16_rn(e2), __float2bfloat16_rn(e3));
    }
  }
  rsum0 += __shfl_xor_sync(0xffffffffu, rsum0, 1);
  rsum0 += __shfl_xor_sync(0xffffffffu, rsum0, 2);
  rsum1 += __shfl_xor_sync(0xffffffffu, rsum1, 1);
  rsum1 += __shfl_xor_sync(0xffffffffu, rsum1, 2);
  if (tig == 0) {
    rinvA[m0r]     = 1.0f / rsum0;
    rinvA[m0r + 8] = 1.0f / rsum1;
  }
  __syncthreads();
  {
    const int col = tid >> 1, r0 = (tid & 1)*98;
    float cs = 0.f;
    for (int r = r0; r < r0 + 98; ++r)
      cs += __bfloat162float(Sm[(size_t)r*KB_SSTR + col]);
    cs += __shfl_xor_sync(0xffffffffu, cs, 1);
    if ((tid & 1) == 0) cinvA[col] = 1.0f / cs;
  }
  __syncthreads();
  __nv_bfloat16* Pf = g_P + (size_t)(b*S_ + t       )*MP2_;
  __nv_bfloat16* Pb = g_P + (size_t)(b*S_ + (37 - t))*MP2_;
  for (int idx = tid; idx < 224*112; idx += 448) {
    const int r = idx / 112, m2 = (idx - r*112)*2;
    float f0 = 0.f, f1 = 0.f, p0 = 0.f, p1 = 0.f;
    if (r < N_) {
      const float ri = rinvA[r], ci = cinvA[r];
      if (m2 < N_) {
        f0 = __bfloat162float(Sm[(size_t)r*KB_SSTR + m2]) * ri;
        p0 = __bfloat162float(Sm[(size_t)m2*KB_SSTR + r]) * ci;
      }
      if (m2 + 1 < N_) {
        f1 = __bfloat162float(Sm[(size_t)r*KB_SSTR + m2 + 1]) * ri;
        p1 = __bfloat162float(Sm[(size_t)(m2 + 1)*KB_SSTR + r]) * ci;
      }
    }
    *(__nv_bfloat162*)(Pf + (size_t)r*NP_ + m2) =
        __nv_bfloat162(__float2bfloat16_rn(f0), __float2bfloat16_rn(f1));
    *(__nv_bfloat162*)(Pb + (size_t)r*NP_ + m2) =
        __nv_bfloat162(__float2bfloat16_rn(p0), __float2bfloat16_rn(p1));
  }
}

// =============================================================================
// Kernel T: fused triple-product tree level. (unchanged R9)
// =============================================================================
#define T_AROWB 416
#define T_ABYTES (112*T_AROWB)              // 46592
#define T_BROWB 512
#define T_BBYTES (208*T_BROWB)              // 106496
#define SMEM_T_BYTES (T_ABYTES + T_BBYTES)  // 153088

__global__ __launch_bounds__(224) void kT(int level, int Lin) {
  extern __shared__ char smt[];
  const int Lout = (Lin + 2) / 3;

  const __nv_bfloat16* src; __nv_bfloat16* dstb;
  switch (level) {
    case 0:  src = g_P;  dstb = g_b1; break;
    case 1:  src = g_b1; dstb = g_b2; break;
    case 2:  src = g_b2; dstb = g_b1; break;
    default: src = g_b1; dstb = 0;   break;   // level 3 -> fp32 g_At
  }

  const int tile = blockIdx.x;        // 0..1 row halves
  const int p    = blockIdx.y;
  const int b    = blockIdx.z;
  const int tid  = threadIdx.x;
  const int base = 3*p;
  const int rem  = Lin - base;
  const int cnt  = rem < 3 ? rem : 3;
  const int row0 = tile * 112;

  if (cnt == 1) {                     // carry: copy through
    const float4* Sg = (const float4*)(src + ((size_t)b*Lin + base)*MP2_);
    float4*       Dg = (float4*)(dstb + ((size_t)b*Lout + p)*MP2_);
    for (int i = tile*3136 + tid; i < (tile + 1)*3136; i += 224) Dg[i] = Sg[i];
    return;
  }

  const __nv_bfloat16* S0 = src + ((size_t)b*Lin + base    )*MP2_;
  const __nv_bfloat16* S1 = src + ((size_t)b*Lin + base + 1)*MP2_;
  const __nv_bfloat16* S2 = src + ((size_t)b*Lin + base + 2)*MP2_;

  const int lane = tid & 31, w = tid >> 5;
  const int tg1 = (lane >> 3) & 1, tg2 = (lane >> 4) & 1;
  const int g = lane >> 2, tig = lane & 3;
  const int arow  = w*16 + (lane & 7) + tg1*8;
  const int bkoff = (lane & 7) + tg1*8;
  const unsigned aBase = smem_u32p(smt);
  const unsigned bBase = smem_u32p(smt + T_ABYTES);

  auto fillA = [&](const __nv_bfloat16* Ms) {
    const char* Am = (const char*)Ms;
    const int r = tid >> 1, cb = tid & 1;
#pragma unroll
    for (int i = 0; i < 13; ++i) {
      const int c = cb + 2*i;
      cpa16(smt + r*T_AROWB + aphys(c, r)*16, Am + (size_t)(row0 + r)*448 + c*16);
    }
  };
  auto fillB = [&](const __nv_bfloat16* Ms) {
    const char* Bm = (const char*)Ms;
    for (int idx = tid; idx < 208*28; idx += 224) {
      const int r = idx / 28, c = idx - r*28;
      const int ph = (c & ~7) | ((c & 7) ^ (r & 7));
      cpa16(smt + T_ABYTES + r*T_BROWB + ph*16, Bm + (size_t)r*448 + c*16);
    }
  };

  float acc[28][4];
  auto mul = [&]() {
#pragma unroll
    for (int nt = 0; nt < 28; ++nt)
#pragma unroll
      for (int j = 0; j < 4; ++j) acc[nt][j] = 0.f;
#pragma unroll
    for (int kk = 0; kk < 13; ++kk) {
      unsigned aF[4];
      const int ca = kk*2 + tg2;
      ldsm4(aBase + arow*T_AROWB + aphys(ca, arow)*16, aF);
      const int brow = kk*16 + bkoff;
      const unsigned bRow = bBase + brow*T_BROWB;
      const int ksw = brow & 7;
#pragma unroll
      for (int jp = 0; jp < 14; ++jp) {
        const int cH = 2*jp + tg2;
        const int ph = (cH & ~7) | ((cH & 7) ^ ksw);
        unsigned bb[4];
        ldsm4t(bRow + ph*16, bb);
        mma_bf16(acc[2*jp    ], aF, bb[0], bb[1]);
        mma_bf16(acc[2*jp + 1], aF, bb[2], bb[3]);
      }
    }
  };

  // stage 1
  if (cnt == 3) { fillA(S2); fillB(S1); }
  else          { fillA(S1); fillB(S0); }
  asm volatile("cp.async.commit_group;\n" ::: "memory");
  asm volatile("cp.async.wait_group 0;\n" ::: "memory");
  __syncthreads();
  mul();

  if (cnt == 3) {
    const int m0r = w*16 + g;
#pragma unroll
    for (int nt = 0; nt < 26; ++nt) {
      const int ph = aphys(nt, m0r);
      *(__nv_bfloat162*)(smt + m0r*T_AROWB + ph*16 + tig*4) =
          __nv_bfloat162(__float2bfloat16_rn(acc[nt][0]), __float2bfloat16_rn(acc[nt][1]));
      *(__nv_bfloat162*)(smt + (m0r + 8)*T_AROWB + ph*16 + tig*4) =
          __nv_bfloat162(__float2bfloat16_rn(acc[nt][2]), __float2bfloat16_rn(acc[nt][3]));
    }
    __syncthreads();
    fillB(S0);
    asm volatile("cp.async.commit_group;\n" ::: "memory");
    asm volatile("cp.async.wait_group 0;\n" ::: "memory");
    __syncthreads();
    mul();                                     // D = M @ A0
  }

  // store
  const int r0g = row0 + w*16 + g;
  if (level < 3) {
    __nv_bfloat16* Cm = dstb + ((size_t)b*Lout + p)*MP2_;
#pragma unroll
    for (int nt = 0; nt < 28; ++nt) {
      const int col = nt*8 + 2*tig;
      *(__nv_bfloat162*)(Cm + (size_t)r0g*NP_ + col) =
          __nv_bfloat162(__float2bfloat16_rn(acc[nt][0]), __float2bfloat16_rn(acc[nt][1]));
      *(__nv_bfloat162*)(Cm + (size_t)(r0g + 8)*NP_ + col) =
          __nv_bfloat162(__float2bfloat16_rn(acc[nt][2]), __float2bfloat16_rn(acc[nt][3]));
    }
  } else {
    float* Cm = g_At + (size_t)b*MP2_;
#pragma unroll
    for (int nt = 0; nt < 28; ++nt) {
      const int col = nt*8 + 2*tig;
      *(float2*)(Cm + (size_t)r0g*NP_ + col)       = make_float2(acc[nt][0], acc[nt][1]);
      *(float2*)(Cm + (size_t)(r0g + 8)*NP_ + col) = make_float2(acc[nt][2], acc[nt][3]);
    }
  }
}

// =============================================================================
// Kernel D: per-row loss/acc, smem-staged coalesced loads. (unchanged R9)
// =============================================================================
#define SMEM_D_BYTES (N_*197*sizeof(float))

__global__ __launch_bounds__(224) void kD() {
  extern __shared__ float sd[];              // [196][197]
  __shared__ float sl[N_], sa[N_];
  const int b = blockIdx.x, tid = threadIdx.x;
  const float* At = g_At + (size_t)b*MP2_;
  for (int idx = tid; idx < N_*N_; idx += 224) {
    const int r = idx / N_, m = idx - r*N_;
    sd[r*197 + m] = At[(size_t)r*NP_ + m];
  }
  __syncthreads();
  if (tid < N_) {
    const float* row = sd + tid*197;
    float rs = 0.f, best = -1.f;
    int bi = 0;
    for (int m = 0; m < N_; ++m) {
      const float v = row[m];
      rs += v;
      if (v > best) { best = v; bi = m; }
    }
    const float diag = row[tid];
    sl[tid] = logf(rs + (float)N_ * EPS_) - logf(diag + EPS_);
    sa[tid] = (bi == tid) ? 1.f : 0.f;
  }
  __syncthreads();
  if (tid == 0) {
    float L = 0.f, A = 0.f;
    for (int i = 0; i < N_; ++i) { L += sl[i]; A += sa[i]; }
    g_partial[b]      = L;
    g_partial[B_ + b] = A;
  }
}

__global__ void kE(float* out, int out_size) {
  float L = 0.f, A = 0.f;
  for (int b = 0; b < B_; ++b) { L += g_partial[b]; A += g_partial[B_ + b]; }
  const float inv = 1.0f / (float)(B_ * N_);
  if (out_size > QSIZE)     out[QSIZE]     = L * inv;
  if (out_size > QSIZE + 1) out[QSIZE + 1] = A * inv;
}

// =============================================================================
extern "C" void kernel_launch(void* const* d_in, const int* in_sizes, int n_in,
                              void* d_out, int out_size) {
  const float* maps = (const float*)d_in[0];
  const float* W    = (const float*)d_in[1];
  const float* bias = (const float*)d_in[2];
  float* out = (float*)d_out;

  cudaFuncSetAttribute(kP, cudaFuncAttributeMaxDynamicSharedMemorySize, (int)SMEM_P_BYTES);
  cudaFuncSetAttribute(kG, cudaFuncAttributeMaxDynamicSharedMemorySize, (int)SMEM_G_BYTES);
  cudaFuncSetAttribute(kQ, cudaFuncAttributeMaxDynamicSharedMemorySize, (int)SMEM_Q_BYTES);
  cudaFuncSetAttribute(kB, cudaFuncAttributeMaxDynamicSharedMemorySize, (int)SMEM_B2_BYTES);
  cudaFuncSetAttribute(kT, cudaFuncAttributeMaxDynamicSharedMemorySize, (int)SMEM_T_BYTES);
  cudaFuncSetAttribute(kD, cudaFuncAttributeMaxDynamicSharedMemorySize, (int)SMEM_D_BYTES);

  kP<<<B_*N_, 256, SMEM_P_BYTES>>>(maps);
  kW<<<256, 256>>>(W);
  kG<<<M_/128, 256, SMEM_G_BYTES>>>(bias);
  kB<<<dim3(T_ - 1, B_), 448, SMEM_B2_BYTES>>>();
  kQ<<<dim3(T_, B_), 256, SMEM_Q_BYTES>>>(out);

  // triple-product tree: 38 -> 13 -> 5 -> 2 -> 1
  kT<<<dim3(2, 13, B_), 224, SMEM_T_BYTES>>>(0, 38);
  kT<<<dim3(2,  5, B_), 224, SMEM_T_BYTES>>>(1, 13);
  kT<<<dim3(2,  2, B_), 224, SMEM_T_BYTES>>>(2,  5);
  kT<<<dim3(2,  1, B_), 224, SMEM_T_BYTES>>>(3,  2);

  kD<<<B_, 224, SMEM_D_BYTES>>>();
  kE<<<1, 1>>>(out, out_size);
}

// round 14
// speedup vs baseline: 1.0108x; 1.0108x over previous
#include <cuda_runtime.h>
#include <cuda_bf16.h>
#include <cuda_fp16.h>
#include <math.h>
#include <stdint.h>

#define B_ 16
#define N_ 196
#define C_ 512
#define T_ 20
#define D_ 128
#define S_ 38
#define NP_ 224                    // padded row/col stride for chain matrices
#define MP2_ (NP_*NP_)             // 50176 elems per padded matrix
#define M_ 62720                   // B*N*T rows of the head GEMM (=490*128)
#define QSIZE 8028160              // B*D*T*N
#define INV_TEMP (1.0f/0.07f)
#define EPS_ 1e-20f

// ---------------- scratch (static device globals; no allocation) ----------------
__device__ float g_qA[B_*T_*N_*D_];                                  // [b][t][n][d] fp32
__device__ __align__(256) __nv_bfloat16 g_qbf[B_*T_*N_*D_];          // bf16 copy of q
__device__ __align__(256) __half g_qp1[(size_t)M_*C_];               // pooled acts fp16
__device__ __align__(256) __half g_qp2[(size_t)M_*C_];               // pooled acts fp16 scaled-res
__device__ __align__(256) __half g_W1[C_*D_];                        // W fp16 [c][d]
__device__ __align__(256) __half g_W2[C_*D_];                        // W fp16 scaled-res
__device__ __align__(256) __nv_bfloat16 g_P [(size_t)B_*S_*MP2_ + 256];
__device__ __align__(256) __nv_bfloat16 g_b1[(size_t)B_*13*MP2_ + 256];
__device__ __align__(256) __nv_bfloat16 g_b2[(size_t)B_*5*MP2_ + 256];
__device__ float g_At[(size_t)B_*MP2_];                              // final product fp32
__device__ float g_partial[2*B_];

// ---------------- mma / ldmatrix / cp.async helpers -------------------------
__device__ __forceinline__ void cpa16(void* dst_smem, const void* src) {
  unsigned d = (unsigned)__cvta_generic_to_shared(dst_smem);
  asm volatile("cp.async.cg.shared.global [%0], [%1], 16;\n" :: "r"(d), "l"(src));
}
__device__ __forceinline__ unsigned smem_u32p(const void* p) {
  return (unsigned)__cvta_generic_to_shared(p);
}
__device__ __forceinline__ void ldsm4(unsigned addr, unsigned* r) {
  asm volatile("ldmatrix.sync.aligned.m8n8.x4.shared.b16 {%0,%1,%2,%3}, [%4];\n"
               : "=r"(r[0]), "=r"(r[1]), "=r"(r[2]), "=r"(r[3]) : "r"(addr));
}
__device__ __forceinline__ void ldsm4t(unsigned addr, unsigned* r) {
  asm volatile("ldmatrix.sync.aligned.m8n8.x4.trans.shared.b16 {%0,%1,%2,%3}, [%4];\n"
               : "=r"(r[0]), "=r"(r[1]), "=r"(r[2]), "=r"(r[3]) : "r"(addr));
}
__device__ __forceinline__ void mma_bf16(float* d, const unsigned* a,
                                         unsigned b0, unsigned b1) {
  asm volatile(
      "mma.sync.aligned.m16n8k16.row.col.f32.bf16.bf16.f32 "
      "{%0,%1,%2,%3}, {%4,%5,%6,%7}, {%8,%9}, {%0,%1,%2,%3};\n"
      : "+f"(d[0]), "+f"(d[1]), "+f"(d[2]), "+f"(d[3])
      : "r"(a[0]), "r"(a[1]), "r"(a[2]), "r"(a[3]), "r"(b0), "r"(b1));
}
__device__ __forceinline__ void mma_f16(float* d, const unsigned* a,
                                        unsigned b0, unsigned b1) {
  asm volatile(
      "mma.sync.aligned.m16n8k16.row.col.f32.f16.f16.f32 "
      "{%0,%1,%2,%3}, {%4,%5,%6,%7}, {%8,%9}, {%0,%1,%2,%3};\n"
      : "+f"(d[0]), "+f"(d[1]), "+f"(d[2]), "+f"(d[3])
      : "r"(a[0]), "r"(a[1]), "r"(a[2]), "r"(a[3]), "r"(b0), "r"(b1));
}
__device__ __forceinline__ int aphys(int c, int r) {
  return (c < 24) ? ((c & ~7) | ((c & 7) ^ (r & 7))) : c;
}

// =============================================================================
// Kernel P: spatial pool + fp16 2-plane split of pooled activations.
// A1 = fp16(x); A2 = fp16(x + 255*(x - A1))  (= AH + 256*AL).
// =============================================================================
#define SMEM_P_BYTES (C_*21*sizeof(float))

__global__ __launch_bounds__(256) void kP(const float* __restrict__ maps) {
  extern __shared__ float qp[];             // [c][t] stride 21
  const int bn = blockIdx.x, tid = threadIdx.x;
  const float4* src = reinterpret_cast<const float4*>(maps) + (size_t)bn * (C_*T_);
  for (int i = tid; i < C_*T_; i += 256) {
    float4 v = src[i];
    const int c = i / 20, t = i - c*20;
    qp[c*21 + t] = (v.x + v.y + v.z + v.w) * 0.25f;
  }
  __syncthreads();
  __half* A1 = g_qp1 + (size_t)bn*20*C_;
  __half* A2 = g_qp2 + (size_t)bn*20*C_;
  for (int i = tid; i < 20*C_; i += 256) {
    const int t = i >> 9, c = i & 511;
    const float x = qp[c*21 + t];
    const __half h = __float2half_rn(x);
    A1[t*C_ + c] = h;
    A2[t*C_ + c] = __float2half_rn(x + 255.0f*(x - __half2float(h)));
  }
}

// W split: W1/W2 fp16 planes ([c][d] layout, row-major in c)
__global__ void kW(const float* __restrict__ W) {
  const int i = blockIdx.x*256 + threadIdx.x;   // grid 256 x 256 = 65536
  const float x = W[i];
  const __half h = __float2half_rn(x);
  g_W1[i] = h;
  g_W2[i] = __float2half_rn(x + 255.0f*(x - __half2float(h)));
}

// =============================================================================
// Kernel G v3: head GEMM, fp16 2-pass scaled split, occupancy-restored.
// CTA 64m x 128n, 256 thr (8 warps = 4 m-tiles x 2 n-halves), warp 16m x 64n,
// 64 acc regs -> 2 CTAs/SM. P1 = A1@W1, P2 = A2@W2; y = P1 + (P2-P1)/256.
// K chunk 32, double buffered. Fused bias + L2 norm epilogue.
// =============================================================================
#define GSTAGE 26624                        // A planes 2x5120 + B planes 2x8192
#define SMEM_G_BYTES (2*GSTAGE)             // 53248

__global__ __launch_bounds__(256, 2) void kG(const float* __restrict__ bias) {
  extern __shared__ char smg[];
  const int m0  = blockIdx.x * 64;
  const int tid = threadIdx.x;
  const int lane = tid & 31, w = tid >> 5;
  const int wm = w & 3, nh = w >> 2;
  const int g = lane >> 2, tig = lane & 3;
  const int tg1 = (lane >> 3) & 1, tg2 = (lane >> 4) & 1;

  const __half* Am1 = g_qp1 + (size_t)m0*C_;
  const __half* Am2 = g_qp2 + (size_t)m0*C_;

  float acc1[8][4], acc2[8][4];
#pragma unroll
  for (int nt = 0; nt < 8; ++nt)
#pragma unroll
    for (int j = 0; j < 4; ++j) { acc1[nt][j] = 0.f; acc2[nt][j] = 0.f; }

  auto fill = [&](int stg, int k0) {
    char* S = smg + stg*GSTAGE;
    // A planes: 64 rows x 4 chunks(16B) x 2 planes = 512 ops (2/thread)
#pragma unroll
    for (int i = 0; i < 2; ++i) {
      const int idx = tid + i*256;
      const int r = idx >> 3, z = idx & 7;
      const int pl = z >> 2, c = z & 3;
      cpa16(S + pl*5120 + r*80 + c*16,
            (pl ? Am2 : Am1) + (size_t)r*C_ + k0 + c*8);
    }
    // B planes: 32 rows x 16 chunks x 2 planes = 1024 ops (4/thread)
#pragma unroll
    for (int i = 0; i < 4; ++i) {
      const int idx = tid + i*256;
      const int r = idx >> 5, z = idx & 31;
      const int pl = z >> 4, c = z & 15;
      const int ph = (c & 8) | ((c & 7) ^ (r & 7));
      cpa16(S + 10240 + pl*8192 + r*256 + ph*16,
            (pl ? g_W2 : g_W1) + (size_t)(k0 + r)*D_ + c*8);
    }
    asm volatile("cp.async.commit_group;\n" ::: "memory");
  };

  fill(0, 0);
  for (int s = 0; s < 16; ++s) {
    if (s + 1 < 16) {
      fill((s + 1) & 1, (s + 1)*32);
      asm volatile("cp.async.wait_group 1;\n" ::: "memory");
    } else {
      asm volatile("cp.async.wait_group 0;\n" ::: "memory");
    }
    __syncthreads();

    const char* S = smg + (s & 1)*GSTAGE;
    const unsigned sBase = smem_u32p(S);
    const int arow = wm*16 + (lane & 7) + tg1*8;

#pragma unroll
    for (int ks = 0; ks < 2; ++ks) {
      unsigned a1[4], a2[4];
      {
        const unsigned ar = sBase + arow*80 + (ks*2 + tg2)*16;
        ldsm4(ar, a1);
        ldsm4(ar + 5120, a2);
      }
      const int brow = ks*16 + (lane & 7) + tg1*8;
#pragma unroll
      for (int jp = 0; jp < 4; ++jp) {
        const int c  = nh*8 + 2*jp + tg2;
        const int ph = (c & 8) | ((c & 7) ^ (brow & 7));
        const unsigned ba = sBase + 10240 + brow*256 + ph*16;
        unsigned b1[4], b2[4];
        ldsm4t(ba, b1);
        ldsm4t(ba + 8192, b2);
        mma_f16(acc1[2*jp    ], a1, b1[0], b1[1]);
        mma_f16(acc1[2*jp + 1], a1, b1[2], b1[3]);
        mma_f16(acc2[2*jp    ], a2, b2[0], b2[1]);
        mma_f16(acc2[2*jp + 1], a2, b2[2], b2[3]);
      }
    }
    __syncthreads();
  }

  // ---- fused epilogue: combine passes, +bias, row L2 norm, write q ----
  float* y       = (float*)smg;            // [64][129]
  float* partial = y + 64*129;             // [64][4]
  float* inorm   = partial + 256;          // [64]
  const float inv256 = 1.0f/256.0f;
  {
    const int row = wm*16 + g;
#pragma unroll
    for (int nt = 0; nt < 8; ++nt) {
      const int col = nh*64 + nt*8 + 2*tig;
      const float* p1 = acc1[nt];
      const float* p2 = acc2[nt];
      y[ row     *129 + col    ] = p1[0] + (p2[0] - p1[0])*inv256;
      y[ row     *129 + col + 1] = p1[1] + (p2[1] - p1[1])*inv256;
      y[(row + 8)*129 + col    ] = p1[2] + (p2[2] - p1[2])*inv256;
      y[(row + 8)*129 + col + 1] = p1[3] + (p2[3] - p1[3])*inv256;
    }
  }
  __syncthreads();
  {
    const int r = tid >> 2, hf = tid & 3;
    float ssum = 0.f;
#pragma unroll 8
    for (int d = hf*32; d < hf*32 + 32; ++d) {
      const float v = y[r*129 + d] + bias[d];
      y[r*129 + d] = v;
      ssum += v*v;
    }
    partial[r*4 + hf] = ssum;
  }
  __syncthreads();
  if (tid < 64)
    inorm[tid] = 1.0f / fmaxf(sqrtf(partial[tid*4] + partial[tid*4 + 1] +
                                    partial[tid*4 + 2] + partial[tid*4 + 3]), 1e-12f);
  __syncthreads();
  for (int i = tid; i < 64*128; i += 256) {
    const int rr = i >> 7, d = i & 127;
    const int m  = m0 + rr;
    const int bn = m / 20, t = m - bn*20;
    const int bq = bn / N_, n = bn - bq*N_;
    const float v = y[rr*129 + d] * inorm[rr];
    const size_t qi = ((size_t)(bq*T_ + t)*N_ + n)*D_ + d;
    g_qA[qi]  = v;
    g_qbf[qi] = __float2bfloat16_rn(v);
  }
}

// =============================================================================
// Kernel Q: transpose q to output layout (B, d, T, N). (unchanged)
// =============================================================================
#define SMEM_Q_BYTES (N_*129*sizeof(float))

__global__ __launch_bounds__(256) void kQ(float* __restrict__ qout) {
  extern __shared__ float sq[];            // [n][d] stride 129
  const int t = blockIdx.x, b = blockIdx.y, tid = threadIdx.x;
  const float* src = g_qA + ((size_t)(b*T_ + t)*N_)*D_;
  for (int i = tid; i < N_*D_; i += 256) {
    const int n = i >> 7, d = i & 127;
    sq[n*129 + d] = src[i];
  }
  __syncthreads();
  for (int i = tid; i < N_*D_; i += 256) {
    const int d = i / N_, n = i - d*N_;
    qout[((size_t)(b*D_ + d)*T_ + t)*N_ + n] = sq[n*129 + d];
  }
}

// =============================================================================
// Kernel B: affinity + palindrome softmax on tensor cores. (unchanged R8)
// =============================================================================
#define KB_A_OFF 0
#define KB_B_OFF 57344                      // 224 rows x 256 B
#define KB_SM_OFF 114688
#define KB_SSTR 232                         // Sm bf16 col stride
#define SMEM_B2_BYTES (KB_SM_OFF + 224*KB_SSTR*2)   // 218624

__global__ __launch_bounds__(448, 1) void kB() {
  extern __shared__ char smb[];
  __shared__ float rinvA[224], cinvA[224];

  const int t = blockIdx.x, b = blockIdx.y, tid = threadIdx.x;
  const int lane = tid & 31, w = tid >> 5;
  const int g = lane >> 2, tig = lane & 3;

  {
    float4 z = make_float4(0.f, 0.f, 0.f, 0.f);
    ((float4*)(smb + KB_A_OFF + 196*256))[tid] = z;
    ((float4*)(smb + KB_B_OFF + 196*256))[tid] = z;
  }
  const __nv_bfloat16* Qa = g_qbf + ((size_t)(b*T_ + t    )*N_)*D_;
  const __nv_bfloat16* Qb = g_qbf + ((size_t)(b*T_ + t + 1)*N_)*D_;
  for (int idx = tid; idx < 196*16; idx += 448) {
    const int r = idx >> 4, c = idx & 15;
    const int ph = ((c & 7) ^ (r & 7)) | (c & 8);
    cpa16(smb + KB_A_OFF + r*256 + ph*16, Qa + (size_t)r*D_ + c*8);
    cpa16(smb + KB_B_OFF + r*256 + ph*16, Qb + (size_t)r*D_ + c*8);
  }
  asm volatile("cp.async.commit_group;\n" ::: "memory");
  asm volatile("cp.async.wait_group 0;\n" ::: "memory");
  __syncthreads();

  unsigned aF[8][4];
  {
    const int r = w*16 + (lane & 7) + ((lane >> 3) & 1)*8;
#pragma unroll
    for (int ks = 0; ks < 8; ++ks) {
      const int c  = 2*ks + ((lane >> 4) & 1);
      const int ph = ((c & 7) ^ (r & 7)) | (c & 8);
      ldsm4(smem_u32p(smb + KB_A_OFF) + r*256 + ph*16, aF[ks]);
    }
  }

  const unsigned bBase = smem_u32p(smb + KB_B_OFF);
  __nv_bfloat16* Sm = (__nv_bfloat16*)(smb + KB_SM_OFF);
  const int m0r = w*16 + g;
  float rsum0 = 0.f, rsum1 = 0.f;

  const int brlo = (lane & 7) + ((lane >> 4) & 1)*8;
  const int bchi = (lane >> 3) & 1;

  for (int ch = 0; ch < 7; ++ch) {
    float acc[4][4];
#pragma unroll
    for (int nt = 0; nt < 4; ++nt)
#pragma unroll
      for (int j = 0; j < 4; ++j) acc[nt][j] = 0.f;

#pragma unroll
    for (int ks = 0; ks < 8; ++ks) {
#pragma unroll
      for (int half = 0; half < 2; ++half) {
        const int r  = ch*32 + half*16 + brlo;
        const int c  = 2*ks + bchi;
        const int ph = ((c & 7) ^ (r & 7)) | (c & 8);
        unsigned bf[4];
        ldsm4(bBase + r*256 + ph*16, bf);
        mma_bf16(acc[half*2    ], aF[ks], bf[0], bf[1]);
        mma_bf16(acc[half*2 + 1], aF[ks], bf[2], bf[3]);
      }
    }
#pragma unroll
    for (int nt = 0; nt < 4; ++nt) {
      const int col = ch*32 + nt*8 + 2*tig;
      const float e0 = __expf(acc[nt][0]*INV_TEMP);
      const float e1 = __expf(acc[nt][1]*INV_TEMP);
      const float e2 = __expf(acc[nt][2]*INV_TEMP);
      const float e3 = __expf(acc[nt][3]*INV_TEMP);
      if (col     < N_) { rsum0 += e0; rsum1 += e2; }
      if (col + 1 < N_) { rsum0 += e1; rsum1 += e3; }
      *(__nv_bfloat162*)(Sm + (size_t)m0r*KB_SSTR + col) =
          __nv_bfloat162(__float2bfloat16_rn(e0), __float2bfloat16_rn(e1));
      *(__nv_bfloat162*)(Sm + (size_t)(m0r + 8)*KB_SSTR + col) =
          __nv_bfloat162(__float2bfloat16_rn(e2), __float2bfloat16_rn(e3));
    }
  }
  rsum0 += __shfl_xor_sync(0xffffffffu, rsum0, 1);
  rsum0 += __shfl_xor_sync(0xffffffffu, rsum0, 2);
  rsum1 += __shfl_xor_sync(0xffffffffu, rsum1, 1);
  rsum1 += __shfl_xor_sync(0xffffffffu, rsum1, 2);
  if (tig == 0) {
    rinvA[m0r]     = 1.0f / rsum0;
    rinvA[m0r + 8] = 1.0f / rsum1;
  }
  __syncthreads();
  {
    const int col = tid >> 1, r0 = (tid & 1)*98;
    float cs = 0.f;
    for (int r = r0; r < r0 + 98; ++r)
      cs += __bfloat162float(Sm[(size_t)r*KB_SSTR + col]);
    cs += __shfl_xor_sync(0xffffffffu, cs, 1);
    if ((tid & 1) == 0) cinvA[col] = 1.0f / cs;
  }
  __syncthreads();
  __nv_bfloat16* Pf = g_P + (size_t)(b*S_ + t       )*MP2_;
  __nv_bfloat16* Pb = g_P + (size_t)(b*S_ + (37 - t))*MP2_;
  for (int idx = tid; idx < 224*112; idx += 448) {
    const int r = idx / 112, m2 = (idx - r*112)*2;
    float f0 = 0.f, f1 = 0.f, p0 = 0.f, p1 = 0.f;
    if (r < N_) {
      const float ri = rinvA[r], ci = cinvA[r];
      if (m2 < N_) {
        f0 = __bfloat162float(Sm[(size_t)r*KB_SSTR + m2]) * ri;
        p0 = __bfloat162float(Sm[(size_t)m2*KB_SSTR + r]) * ci;
      }
      if (m2 + 1 < N_) {
        f1 = __bfloat162float(Sm[(size_t)r*KB_SSTR + m2 + 1]) * ri;
        p1 = __bfloat162float(Sm[(size_t)(m2 + 1)*KB_SSTR + r]) * ci;
      }
    }
    *(__nv_bfloat162*)(Pf + (size_t)r*NP_ + m2) =
        __nv_bfloat162(__float2bfloat16_rn(f0), __float2bfloat16_rn(f1));
    *(__nv_bfloat162*)(Pb + (size_t)r*NP_ + m2) =
        __nv_bfloat162(__float2bfloat16_rn(p0), __float2bfloat16_rn(p1));
  }
}

// =============================================================================
// Kernel T: fused triple-product tree level. (unchanged R9)
// =============================================================================
#define T_AROWB 416
#define T_ABYTES (112*T_AROWB)              // 46592
#define T_BROWB 512
#define T_BBYTES (208*T_BROWB)              // 106496
#define SMEM_T_BYTES (T_ABYTES + T_BBYTES)  // 153088

__global__ __launch_bounds__(224) void kT(int level, int Lin) {
  extern __shared__ char smt[];
  const int Lout = (Lin + 2) / 3;

  const __nv_bfloat16* src; __nv_bfloat16* dstb;
  switch (level) {
    case 0:  src = g_P;  dstb = g_b1; break;
    case 1:  src = g_b1; dstb = g_b2; break;
    case 2:  src = g_b2; dstb = g_b1; break;
    default: src = g_b1; dstb = 0;   break;   // level 3 -> fp32 g_At
  }

  const int tile = blockIdx.x;        // 0..1 row halves
  const int p    = blockIdx.y;
  const int b    = blockIdx.z;
  const int tid  = threadIdx.x;
  const int base = 3*p;
  const int rem  = Lin - base;
  const int cnt  = rem < 3 ? rem : 3;
  const int row0 = tile * 112;

  if (cnt == 1) {                     // carry: copy through
    const float4* Sg = (const float4*)(src + ((size_t)b*Lin + base)*MP2_);
    float4*       Dg = (float4*)(dstb + ((size_t)b*Lout + p)*MP2_);
    for (int i = tile*3136 + tid; i < (tile + 1)*3136; i += 224) Dg[i] = Sg[i];
    return;
  }

  const __nv_bfloat16* S0 = src + ((size_t)b*Lin + base    )*MP2_;
  const __nv_bfloat16* S1 = src + ((size_t)b*Lin + base + 1)*MP2_;
  const __nv_bfloat16* S2 = src + ((size_t)b*Lin + base + 2)*MP2_;

  const int lane = tid & 31, w = tid >> 5;
  const int tg1 = (lane >> 3) & 1, tg2 = (lane >> 4) & 1;
  const int g = lane >> 2, tig = lane & 3;
  const int arow  = w*16 + (lane & 7) + tg1*8;
  const int bkoff = (lane & 7) + tg1*8;
  const unsigned aBase = smem_u32p(smt);
  const unsigned bBase = smem_u32p(smt + T_ABYTES);

  auto fillA = [&](const __nv_bfloat16* Ms) {
    const char* Am = (const char*)Ms;
    const int r = tid >> 1, cb = tid & 1;
#pragma unroll
    for (int i = 0; i < 13; ++i) {
      const int c = cb + 2*i;
      cpa16(smt + r*T_AROWB + aphys(c, r)*16, Am + (size_t)(row0 + r)*448 + c*16);
    }
  };
  auto fillB = [&](const __nv_bfloat16* Ms) {
    const char* Bm = (const char*)Ms;
    for (int idx = tid; idx < 208*28; idx += 224) {
      const int r = idx / 28, c = idx - r*28;
      const int ph = (c & ~7) | ((c & 7) ^ (r & 7));
      cpa16(smt + T_ABYTES + r*T_BROWB + ph*16, Bm + (size_t)r*448 + c*16);
    }
  };

  float acc[28][4];
  auto mul = [&]() {
#pragma unroll
    for (int nt = 0; nt < 28; ++nt)
#pragma unroll
      for (int j = 0; j < 4; ++j) acc[nt][j] = 0.f;
#pragma unroll
    for (int kk = 0; kk < 13; ++kk) {
      unsigned aF[4];
      const int ca = kk*2 + tg2;
      ldsm4(aBase + arow*T_AROWB + aphys(ca, arow)*16, aF);
      const int brow = kk*16 + bkoff;
      const unsigned bRow = bBase + brow*T_BROWB;
      const int ksw = brow & 7;
#pragma unroll
      for (int jp = 0; jp < 14; ++jp) {
        const int cH = 2*jp + tg2;
        const int ph = (cH & ~7) | ((cH & 7) ^ ksw);
        unsigned bb[4];
        ldsm4t(bRow + ph*16, bb);
        mma_bf16(acc[2*jp    ], aF, bb[0], bb[1]);
        mma_bf16(acc[2*jp + 1], aF, bb[2], bb[3]);
      }
    }
  };

  // stage 1
  if (cnt == 3) { fillA(S2); fillB(S1); }
  else          { fillA(S1); fillB(S0); }
  asm volatile("cp.async.commit_group;\n" ::: "memory");
  asm volatile("cp.async.wait_group 0;\n" ::: "memory");
  __syncthreads();
  mul();

  if (cnt == 3) {
    const int m0r = w*16 + g;
#pragma unroll
    for (int nt = 0; nt < 26; ++nt) {
      const int ph = aphys(nt, m0r);
      *(__nv_bfloat162*)(smt + m0r*T_AROWB + ph*16 + tig*4) =
          __nv_bfloat162(__float2bfloat16_rn(acc[nt][0]), __float2bfloat16_rn(acc[nt][1]));
      *(__nv_bfloat162*)(smt + (m0r + 8)*T_AROWB + ph*16 + tig*4) =
          __nv_bfloat162(__float2bfloat16_rn(acc[nt][2]), __float2bfloat16_rn(acc[nt][3]));
    }
    __syncthreads();
    fillB(S0);
    asm volatile("cp.async.commit_group;\n" ::: "memory");
    asm volatile("cp.async.wait_group 0;\n" ::: "memory");
    __syncthreads();
    mul();                                     // D = M @ A0
  }

  // store
  const int r0g = row0 + w*16 + g;
  if (level < 3) {
    __nv_bfloat16* Cm = dstb + ((size_t)b*Lout + p)*MP2_;
#pragma unroll
    for (int nt = 0; nt < 28; ++nt) {
      const int col = nt*8 + 2*tig;
      *(__nv_bfloat162*)(Cm + (size_t)r0g*NP_ + col) =
          __nv_bfloat162(__float2bfloat16_rn(acc[nt][0]), __float2bfloat16_rn(acc[nt][1]));
      *(__nv_bfloat162*)(Cm + (size_t)(r0g + 8)*NP_ + col) =
          __nv_bfloat162(__float2bfloat16_rn(acc[nt][2]), __float2bfloat16_rn(acc[nt][3]));
    }
  } else {
    float* Cm = g_At + (size_t)b*MP2_;
#pragma unroll
    for (int nt = 0; nt < 28; ++nt) {
      const int col = nt*8 + 2*tig;
      *(float2*)(Cm + (size_t)r0g*NP_ + col)       = make_float2(acc[nt][0], acc[nt][1]);
      *(float2*)(Cm + (size_t)(r0g + 8)*NP_ + col) = make_float2(acc[nt][2], acc[nt][3]);
    }
  }
}

// =============================================================================
// Kernel D: per-row loss/acc, smem-staged coalesced loads. (unchanged R9)
// =============================================================================
#define SMEM_D_BYTES (N_*197*sizeof(float))

__global__ __launch_bounds__(224) void kD() {
  extern __shared__ float sd[];              // [196][197]
  __shared__ float sl[N_], sa[N_];
  const int b = blockIdx.x, tid = threadIdx.x;
  const float* At = g_At + (size_t)b*MP2_;
  for (int idx = tid; idx < N_*N_; idx += 224) {
    const int r = idx / N_, m = idx - r*N_;
    sd[r*197 + m] = At[(size_t)r*NP_ + m];
  }
  __syncthreads();
  if (tid < N_) {
    const float* row = sd + tid*197;
    float rs = 0.f, best = -1.f;
    int bi = 0;
    for (int m = 0; m < N_; ++m) {
      const float v = row[m];
      rs += v;
      if (v > best) { best = v; bi = m; }
    }
    const float diag = row[tid];
    sl[tid] = logf(rs + (float)N_ * EPS_) - logf(diag + EPS_);
    sa[tid] = (bi == tid) ? 1.f : 0.f;
  }
  __syncthreads();
  if (tid == 0) {
    float L = 0.f, A = 0.f;
    for (int i = 0; i < N_; ++i) { L += sl[i]; A += sa[i]; }
    g_partial[b]      = L;
    g_partial[B_ + b] = A;
  }
}

__global__ void kE(float* out, int out_size) {
  float L = 0.f, A = 0.f;
  for (int b = 0; b < B_; ++b) { L += g_partial[b]; A += g_partial[B_ + b]; }
  const float inv = 1.0f / (float)(B_ * N_);
  if (out_size > QSIZE)     out[QSIZE]     = L * inv;
  if (out_size > QSIZE + 1) out[QSIZE + 1] = A * inv;
}

// =============================================================================
extern "C" void kernel_launch(void* const* d_in, const int* in_sizes, int n_in,
                              void* d_out, int out_size) {
  const float* maps = (const float*)d_in[0];
  const float* W    = (const float*)d_in[1];
  const float* bias = (const float*)d_in[2];
  float* out = (float*)d_out;

  cudaFuncSetAttribute(kP, cudaFuncAttributeMaxDynamicSharedMemorySize, (int)SMEM_P_BYTES);
  cudaFuncSetAttribute(kG, cudaFuncAttributeMaxDynamicSharedMemorySize, (int)SMEM_G_BYTES);
  cudaFuncSetAttribute(kQ, cudaFuncAttributeMaxDynamicSharedMemorySize, (int)SMEM_Q_BYTES);
  cudaFuncSetAttribute(kB, cudaFuncAttributeMaxDynamicSharedMemorySize, (int)SMEM_B2_BYTES);
  cudaFuncSetAttribute(kT, cudaFuncAttributeMaxDynamicSharedMemorySize, (int)SMEM_T_BYTES);
  cudaFuncSetAttribute(kD, cudaFuncAttributeMaxDynamicSharedMemorySize, (int)SMEM_D_BYTES);

  kP<<<B_*N_, 256, SMEM_P_BYTES>>>(maps);
  kW<<<256, 256>>>(W);
  kG<<<M_/64, 256, SMEM_G_BYTES>>>(bias);
  kB<<<dim3(T_ - 1, B_), 448, SMEM_B2_BYTES>>>();
  kQ<<<dim3(T_, B_), 256, SMEM_Q_BYTES>>>(out);

  // triple-product tree: 38 -> 13 -> 5 -> 2 -> 1
  kT<<<dim3(2, 13, B_), 224, SMEM_T_BYTES>>>(0, 38);
  kT<<<dim3(2,  5, B_), 224, SMEM_T_BYTES>>>(1, 13);
  kT<<<dim3(2,  2, B_), 224, SMEM_T_BYTES>>>(2,  5);
  kT<<<dim3(2,  1, B_), 224, SMEM_T_BYTES>>>(3,  2);

  kD<<<B_, 224, SMEM_D_BYTES>>>();
  kE<<<1, 1>>>(out, out_size);
}

// round 15
// speedup vs baseline: 1.0152x; 1.0043x over previous
#include <cuda_runtime.h>
#include <cuda_bf16.h>
#include <cuda_fp16.h>
#include <math.h>
#include <stdint.h>

#define B_ 16
#define N_ 196
#define C_ 512
#define T_ 20
#define D_ 128
#define S_ 38
#define NP_ 224                    // padded row/col stride for chain matrices
#define MP2_ (NP_*NP_)             // 50176 elems per padded matrix
#define M_ 62720                   // B*N*T rows of the head GEMM (=490*128)
#define QSIZE 8028160              // B*D*T*N
#define INV_TEMP (1.0f/0.07f)
#define EPS_ 1e-20f

// ---------------- scratch (static device globals; no allocation) ----------------
__device__ float g_qA[B_*T_*N_*D_];                                  // [b][t][n][d] fp32
__device__ __align__(256) __nv_bfloat16 g_qbf[B_*T_*N_*D_];          // bf16 copy of q
__device__ __align__(256) __half g_W1[C_*D_];                        // W fp16 [c][d]
__device__ __align__(256) __half g_W2[C_*D_];                        // W fp16 scaled-res
__device__ __align__(256) __nv_bfloat16 g_P [(size_t)B_*S_*MP2_ + 256];
__device__ __align__(256) __nv_bfloat16 g_b1[(size_t)B_*10*MP2_ + 256];
__device__ __align__(256) __nv_bfloat16 g_b2[(size_t)B_*3*MP2_ + 256];
__device__ float g_At[(size_t)B_*MP2_];                              // final product fp32
__device__ float g_partial[2*B_];

// ---------------- mma / ldmatrix / cp.async helpers -------------------------
__device__ __forceinline__ void cpa16(void* dst_smem, const void* src) {
  unsigned d = (unsigned)__cvta_generic_to_shared(dst_smem);
  asm volatile("cp.async.cg.shared.global [%0], [%1], 16;\n" :: "r"(d), "l"(src));
}
__device__ __forceinline__ unsigned smem_u32p(const void* p) {
  return (unsigned)__cvta_generic_to_shared(p);
}
__device__ __forceinline__ void ldsm4(unsigned addr, unsigned* r) {
  asm volatile("ldmatrix.sync.aligned.m8n8.x4.shared.b16 {%0,%1,%2,%3}, [%4];\n"
               : "=r"(r[0]), "=r"(r[1]), "=r"(r[2]), "=r"(r[3]) : "r"(addr));
}
__device__ __forceinline__ void ldsm4t(unsigned addr, unsigned* r) {
  asm volatile("ldmatrix.sync.aligned.m8n8.x4.trans.shared.b16 {%0,%1,%2,%3}, [%4];\n"
               : "=r"(r[0]), "=r"(r[1]), "=r"(r[2]), "=r"(r[3]) : "r"(addr));
}
__device__ __forceinline__ void mma_bf16(float* d, const unsigned* a,
                                         unsigned b0, unsigned b1) {
  asm volatile(
      "mma.sync.aligned.m16n8k16.row.col.f32.bf16.bf16.f32 "
      "{%0,%1,%2,%3}, {%4,%5,%6,%7}, {%8,%9}, {%0,%1,%2,%3};\n"
      : "+f"(d[0]), "+f"(d[1]), "+f"(d[2]), "+f"(d[3])
      : "r"(a[0]), "r"(a[1]), "r"(a[2]), "r"(a[3]), "r"(b0), "r"(b1));
}
__device__ __forceinline__ void mma_f16(float* d, const unsigned* a,
                                        unsigned b0, unsigned b1) {
  asm volatile(
      "mma.sync.aligned.m16n8k16.row.col.f32.f16.f16.f32 "
      "{%0,%1,%2,%3}, {%4,%5,%6,%7}, {%8,%9}, {%0,%1,%2,%3};\n"
      : "+f"(d[0]), "+f"(d[1]), "+f"(d[2]), "+f"(d[3])
      : "r"(a[0]), "r"(a[1]), "r"(a[2]), "r"(a[3]), "r"(b0), "r"(b1));
}
__device__ __forceinline__ int aphys(int c, int r) {
  return (c < 24) ? ((c & ~7) | ((c & 7) ^ (r & 7))) : c;
}

// W split: W1/W2 fp16 planes ([c][d] layout, row-major in c)
__global__ void kW(const float* __restrict__ W) {
  const int i = blockIdx.x*256 + threadIdx.x;   // grid 256 x 256 = 65536
  const float x = W[i];
  const __half h = __float2half_rn(x);
  g_W1[i] = h;
  g_W2[i] = __float2half_rn(x + 255.0f*(x - __half2float(h)));
}

// =============================================================================
// Kernel G v4: FUSED pool + head GEMM. Reads raw maps directly (sector-aligned
// gather: lanes cover 16 c x one m-pair, adjacent t's are 16B apart), pools +
// fp16 2-plane splits in registers, STS into A operand smem. B (W planes) via
// cp.async. fp16 2-pass scaled split: P1=A1@W1, P2=A2@W2; y = P1+(P2-P1)/256.
// CTA 64m x 128n, 256 thr (8 warps = 4m x 2n). K chunk 32, double buffered,
// LDG prefetch of chunk s+1 overlapped with MMA of chunk s.
// Fused epilogue: +bias, L2 norm, write g_qA + g_qbf.
// =============================================================================
#define GSTAGE 26624                        // A planes 2x5120 + B planes 2x8192
#define SMEM_G_BYTES (2*GSTAGE)             // 53248

__global__ __launch_bounds__(256) void kG(const float* __restrict__ maps,
                                          const float* __restrict__ bias) {
  extern __shared__ char smg[];
  const int m0  = blockIdx.x * 64;
  const int tid = threadIdx.x;
  const int lane = tid & 31, w = tid >> 5;
  const int wm = w & 3, nh = w >> 2;
  const int g = lane >> 2, tig = lane & 3;
  const int tg1 = (lane >> 3) & 1, tg2 = (lane >> 4) & 1;

  // ---- raw maps load setup: thread owns (m_base + 8i, c_loc) for i=0..7 ----
  const int c_loc  = (tid >> 1) & 31;
  const int m_base = ((tid >> 6) << 1) | (tid & 1);
  const float4* maps4 = reinterpret_cast<const float4*>(maps);
  const float4* pbase[8];
#pragma unroll
  for (int i = 0; i < 8; ++i) {
    const int m = m0 + m_base + 8*i;
    const int bn = m / 20, t = m - bn*20;
    pbase[i] = maps4 + (size_t)bn*10240 + (size_t)c_loc*20 + t;
  }
  float4 raw[8];

  auto ldraw = [&](int k0) {
    const int off = k0*20;
#pragma unroll
    for (int i = 0; i < 8; ++i) raw[i] = pbase[i][off];
  };
  auto stsA = [&](char* S) {
#pragma unroll
    for (int i = 0; i < 8; ++i) {
      const float v = (raw[i].x + raw[i].y + raw[i].z + raw[i].w) * 0.25f;
      const __half h1 = __float2half_rn(v);
      const __half h2 = __float2half_rn(v + 255.0f*(v - __half2float(h1)));
      const int ro = (m_base + 8*i)*80 + c_loc*2;
      *(__half*)(S + ro)        = h1;
      *(__half*)(S + 5120 + ro) = h2;
    }
  };
  auto fillB = [&](char* S, int k0) {
#pragma unroll
    for (int i = 0; i < 4; ++i) {          // 32 rows x 16 chunks x 2 planes
      const int idx = tid + i*256;
      const int r = idx >> 5, z = idx & 31;
      const int pl = z >> 4, c = z & 15;
      const int ph = (c & 8) | ((c & 7) ^ (r & 7));
      cpa16(S + 10240 + pl*8192 + r*256 + ph*16,
            (pl ? g_W2 : g_W1) + (size_t)(k0 + r)*D_ + c*8);
    }
    asm volatile("cp.async.commit_group;\n" ::: "memory");
  };

  float acc1[8][4], acc2[8][4];
#pragma unroll
  for (int nt = 0; nt < 8; ++nt)
#pragma unroll
    for (int j = 0; j < 4; ++j) { acc1[nt][j] = 0.f; acc2[nt][j] = 0.f; }

  // prologue
  ldraw(0);
  fillB(smg, 0);
  stsA(smg);

  for (int s = 0; s < 16; ++s) {
    asm volatile("cp.async.wait_group 0;\n" ::: "memory");
    __syncthreads();

    char* Snext = smg + ((s + 1) & 1)*GSTAGE;
    if (s + 1 < 16) {
      ldraw((s + 1)*32);                   // LDGs in flight during MMA
      fillB(Snext, (s + 1)*32);
    }

    const char* S = smg + (s & 1)*GSTAGE;
    const unsigned sBase = smem_u32p(S);
    const int arow = wm*16 + (lane & 7) + tg1*8;
#pragma unroll
    for (int ks = 0; ks < 2; ++ks) {
      unsigned a1[4], a2[4];
      {
        const unsigned ar = sBase + arow*80 + (ks*2 + tg2)*16;
        ldsm4(ar, a1);
        ldsm4(ar + 5120, a2);
      }
      const int brow = ks*16 + (lane & 7) + tg1*8;
#pragma unroll
      for (int jp = 0; jp < 4; ++jp) {
        const int c  = nh*8 + 2*jp + tg2;
        const int ph = (c & 8) | ((c & 7) ^ (brow & 7));
        const unsigned ba = sBase + 10240 + brow*256 + ph*16;
        unsigned b1[4], b2[4];
        ldsm4t(ba, b1);
        ldsm4t(ba + 8192, b2);
        mma_f16(acc1[2*jp    ], a1, b1[0], b1[1]);
        mma_f16(acc1[2*jp + 1], a1, b1[2], b1[3]);
        mma_f16(acc2[2*jp    ], a2, b2[0], b2[1]);
        mma_f16(acc2[2*jp + 1], a2, b2[2], b2[3]);
      }
    }
    if (s + 1 < 16) stsA(Snext);           // raw regs arrive under MMA cover
  }
  __syncthreads();                         // epilogue reuses both stages

  // ---- fused epilogue: combine passes, +bias, row L2 norm, write q ----
  float* y       = (float*)smg;            // [64][129]
  float* partial = y + 64*129;             // [64][4]
  float* inorm   = partial + 256;          // [64]
  const float inv256 = 1.0f/256.0f;
  {
    const int row = wm*16 + g;
#pragma unroll
    for (int nt = 0; nt < 8; ++nt) {
      const int col = nh*64 + nt*8 + 2*tig;
      const float* p1 = acc1[nt];
      const float* p2 = acc2[nt];
      y[ row     *129 + col    ] = p1[0] + (p2[0] - p1[0])*inv256;
      y[ row     *129 + col + 1] = p1[1] + (p2[1] - p1[1])*inv256;
      y[(row + 8)*129 + col    ] = p1[2] + (p2[2] - p1[2])*inv256;
      y[(row + 8)*129 + col + 1] = p1[3] + (p2[3] - p1[3])*inv256;
    }
  }
  __syncthreads();
  {
    const int r = tid >> 2, hf = tid & 3;
    float ssum = 0.f;
#pragma unroll 8
    for (int d = hf*32; d < hf*32 + 32; ++d) {
      const float v = y[r*129 + d] + bias[d];
      y[r*129 + d] = v;
      ssum += v*v;
    }
    partial[r*4 + hf] = ssum;
  }
  __syncthreads();
  if (tid < 64)
    inorm[tid] = 1.0f / fmaxf(sqrtf(partial[tid*4] + partial[tid*4 + 1] +
                                    partial[tid*4 + 2] + partial[tid*4 + 3]), 1e-12f);
  __syncthreads();
  for (int i = tid; i < 64*128; i += 256) {
    const int rr = i >> 7, d = i & 127;
    const int m  = m0 + rr;
    const int bn = m / 20, t = m - bn*20;
    const int bq = bn / N_, n = bn - bq*N_;
    const float v = y[rr*129 + d] * inorm[rr];
    const size_t qi = ((size_t)(bq*T_ + t)*N_ + n)*D_ + d;
    g_qA[qi]  = v;
    g_qbf[qi] = __float2bfloat16_rn(v);
  }
}

// =============================================================================
// Kernel Q: transpose q to output layout (B, d, T, N). (unchanged)
// =============================================================================
#define SMEM_Q_BYTES (N_*129*sizeof(float))

__global__ __launch_bounds__(256) void kQ(float* __restrict__ qout) {
  extern __shared__ float sq[];            // [n][d] stride 129
  const int t = blockIdx.x, b = blockIdx.y, tid = threadIdx.x;
  const float* src = g_qA + ((size_t)(b*T_ + t)*N_)*D_;
  for (int i = tid; i < N_*D_; i += 256) {
    const int n = i >> 7, d = i & 127;
    sq[n*129 + d] = src[i];
  }
  __syncthreads();
  for (int i = tid; i < N_*D_; i += 256) {
    const int d = i / N_, n = i - d*N_;
    qout[((size_t)(b*D_ + d)*T_ + t)*N_ + n] = sq[n*129 + d];
  }
}

// =============================================================================
// Kernel B: affinity + palindrome softmax on tensor cores. (unchanged R8)
// =============================================================================
#define KB_A_OFF 0
#define KB_B_OFF 57344                      // 224 rows x 256 B
#define KB_SM_OFF 114688
#define KB_SSTR 232                         // Sm bf16 col stride
#define SMEM_B2_BYTES (KB_SM_OFF + 224*KB_SSTR*2)   // 218624

__global__ __launch_bounds__(448, 1) void kB() {
  extern __shared__ char smb[];
  __shared__ float rinvA[224], cinvA[224];

  const int t = blockIdx.x, b = blockIdx.y, tid = threadIdx.x;
  const int lane = tid & 31, w = tid >> 5;
  const int g = lane >> 2, tig = lane & 3;

  {
    float4 z = make_float4(0.f, 0.f, 0.f, 0.f);
    ((float4*)(smb + KB_A_OFF + 196*256))[tid] = z;
    ((float4*)(smb + KB_B_OFF + 196*256))[tid] = z;
  }
  const __nv_bfloat16* Qa = g_qbf + ((size_t)(b*T_ + t    )*N_)*D_;
  const __nv_bfloat16* Qb = g_qbf + ((size_t)(b*T_ + t + 1)*N_)*D_;
  for (int idx = tid; idx < 196*16; idx += 448) {
    const int r = idx >> 4, c = idx & 15;
    const int ph = ((c & 7) ^ (r & 7)) | (c & 8);
    cpa16(smb + KB_A_OFF + r*256 + ph*16, Qa + (size_t)r*D_ + c*8);
    cpa16(smb + KB_B_OFF + r*256 + ph*16, Qb + (size_t)r*D_ + c*8);
  }
  asm volatile("cp.async.commit_group;\n" ::: "memory");
  asm volatile("cp.async.wait_group 0;\n" ::: "memory");
  __syncthreads();

  unsigned aF[8][4];
  {
    const int r = w*16 + (lane & 7) + ((lane >> 3) & 1)*8;
#pragma unroll
    for (int ks = 0; ks < 8; ++ks) {
      const int c  = 2*ks + ((lane >> 4) & 1);
      const int ph = ((c & 7) ^ (r & 7)) | (c & 8);
      ldsm4(smem_u32p(smb + KB_A_OFF) + r*256 + ph*16, aF[ks]);
    }
  }

  const unsigned bBase = smem_u32p(smb + KB_B_OFF);
  __nv_bfloat16* Sm = (__nv_bfloat16*)(smb + KB_SM_OFF);
  const int m0r = w*16 + g;
  float rsum0 = 0.f, rsum1 = 0.f;

  const int brlo = (lane & 7) + ((lane >> 4) & 1)*8;
  const int bchi = (lane >> 3) & 1;

  for (int ch = 0; ch < 7; ++ch) {
    float acc[4][4];
#pragma unroll
    for (int nt = 0; nt < 4; ++nt)
#pragma unroll
      for (int j = 0; j < 4; ++j) acc[nt][j] = 0.f;

#pragma unroll
    for (int ks = 0; ks < 8; ++ks) {
#pragma unroll
      for (int half = 0; half < 2; ++half) {
        const int r  = ch*32 + half*16 + brlo;
        const int c  = 2*ks + bchi;
        const int ph = ((c & 7) ^ (r & 7)) | (c & 8);
        unsigned bf[4];
        ldsm4(bBase + r*256 + ph*16, bf);
        mma_bf16(acc[half*2    ], aF[ks], bf[0], bf[1]);
        mma_bf16(acc[half*2 + 1], aF[ks], bf[2], bf[3]);
      }
    }
#pragma unroll
    for (int nt = 0; nt < 4; ++nt) {
      const int col = ch*32 + nt*8 + 2*tig;
      const float e0 = __expf(acc[nt][0]*INV_TEMP);
      const float e1 = __expf(acc[nt][1]*INV_TEMP);
      const float e2 = __expf(acc[nt][2]*INV_TEMP);
      const float e3 = __expf(acc[nt][3]*INV_TEMP);
      if (col     < N_) { rsum0 += e0; rsum1 += e2; }
      if (col + 1 < N_) { rsum0 += e1; rsum1 += e3; }
      *(__nv_bfloat162*)(Sm + (size_t)m0r*KB_SSTR + col) =
          __nv_bfloat162(__float2bfloat16_rn(e0), __float2bfloat16_rn(e1));
      *(__nv_bfloat162*)(Sm + (size_t)(m0r + 8)*KB_SSTR + col) =
          __nv_bfloat162(__float2bfloat16_rn(e2), __float2bfloat16_rn(e3));
    }
  }
  rsum0 += __shfl_xor_sync(0xffffffffu, rsum0, 1);
  rsum0 += __shfl_xor_sync(0xffffffffu, rsum0, 2);
  rsum1 += __shfl_xor_sync(0xffffffffu, rsum1, 1);
  rsum1 += __shfl_xor_sync(0xffffffffu, rsum1, 2);
  if (tig == 0) {
    rinvA[m0r]     = 1.0f / rsum0;
    rinvA[m0r + 8] = 1.0f / rsum1;
  }
  __syncthreads();
  {
    const int col = tid >> 1, r0 = (tid & 1)*98;
    float cs = 0.f;
    for (int r = r0; r < r0 + 98; ++r)
      cs += __bfloat162float(Sm[(size_t)r*KB_SSTR + col]);
    cs += __shfl_xor_sync(0xffffffffu, cs, 1);
    if ((tid & 1) == 0) cinvA[col] = 1.0f / cs;
  }
  __syncthreads();
  __nv_bfloat16* Pf = g_P + (size_t)(b*S_ + t       )*MP2_;
  __nv_bfloat16* Pb = g_P + (size_t)(b*S_ + (37 - t))*MP2_;
  for (int idx = tid; idx < 224*112; idx += 448) {
    const int r = idx / 112, m2 = (idx - r*112)*2;
    float f0 = 0.f, f1 = 0.f, p0 = 0.f, p1 = 0.f;
    if (r < N_) {
      const float ri = rinvA[r], ci = cinvA[r];
      if (m2 < N_) {
        f0 = __bfloat162float(Sm[(size_t)r*KB_SSTR + m2]) * ri;
        p0 = __bfloat162float(Sm[(size_t)m2*KB_SSTR + r]) * ci;
      }
      if (m2 + 1 < N_) {
        f1 = __bfloat162float(Sm[(size_t)r*KB_SSTR + m2 + 1]) * ri;
        p1 = __bfloat162float(Sm[(size_t)(m2 + 1)*KB_SSTR + r]) * ci;
      }
    }
    *(__nv_bfloat162*)(Pf + (size_t)r*NP_ + m2) =
        __nv_bfloat162(__float2bfloat16_rn(f0), __float2bfloat16_rn(f1));
    *(__nv_bfloat162*)(Pb + (size_t)r*NP_ + m2) =
        __nv_bfloat162(__float2bfloat16_rn(p0), __float2bfloat16_rn(p1));
  }
}

// =============================================================================
// Kernel T v2: fused GROUP-product tree level (group = up to 4 factors, i.e.
// up to 3 chained muls per CTA). Levels: 38 -> 10 -> 3 -> 1 (no carries).
// out_p = src[base+cnt-1] @ ... @ src[base], base = group*p.
// CTA = 112 rows x 224 cols, 224 thr (7 warps x 16 rows), 112 accs/thr.
// Intermediate M written back into warp-private A-slot rows (no CTA sync for A).
// =============================================================================
#define T_AROWB 416
#define T_ABYTES (112*T_AROWB)              // 46592
#define T_BROWB 512
#define T_BBYTES (208*T_BROWB)              // 106496
#define SMEM_T_BYTES (T_ABYTES + T_BBYTES)  // 153088

__global__ __launch_bounds__(224) void kT(int level, int Lin, int Lout, int group) {
  extern __shared__ char smt[];

  const __nv_bfloat16* src; __nv_bfloat16* dstb;
  switch (level) {
    case 0:  src = g_P;  dstb = g_b1; break;
    case 1:  src = g_b1; dstb = g_b2; break;
    default: src = g_b2; dstb = 0;   break;   // final level -> fp32 g_At
  }
  const bool final_lvl = (level >= 2);

  const int tile = blockIdx.x;        // 0..1 row halves
  const int p    = blockIdx.y;
  const int b    = blockIdx.z;
  const int tid  = threadIdx.x;
  const int base = group*p;
  int cnt = Lin - base; if (cnt > group) cnt = group;   // always >= 2 by construction
  const int row0 = tile * 112;

  const int lane = tid & 31, w = tid >> 5;
  const int tg1 = (lane >> 3) & 1, tg2 = (lane >> 4) & 1;
  const int g = lane >> 2, tig = lane & 3;
  const int arow  = w*16 + (lane & 7) + tg1*8;
  const int bkoff = (lane & 7) + tg1*8;
  const unsigned aBase = smem_u32p(smt);
  const unsigned bBase = smem_u32p(smt + T_ABYTES);

  auto Sp = [&](int j) { return src + ((size_t)b*Lin + base + j)*MP2_; };

  auto fillA = [&](const __nv_bfloat16* Ms) {
    const char* Am = (const char*)Ms;
    const int r = tid >> 1, cb = tid & 1;
#pragma unroll
    for (int i = 0; i < 13; ++i) {
      const int c = cb + 2*i;
      cpa16(smt + r*T_AROWB + aphys(c, r)*16, Am + (size_t)(row0 + r)*448 + c*16);
    }
  };
  auto fillB = [&](const __nv_bfloat16* Ms) {
    const char* Bm = (const char*)Ms;
    for (int idx = tid; idx < 208*28; idx += 224) {
      const int r = idx / 28, c = idx - r*28;
      const int ph = (c & ~7) | ((c & 7) ^ (r & 7));
      cpa16(smt + T_ABYTES + r*T_BROWB + ph*16, Bm + (size_t)r*448 + c*16);
    }
  };

  float acc[28][4];
  auto mul = [&]() {
#pragma unroll
    for (int nt = 0; nt < 28; ++nt)
#pragma unroll
      for (int j = 0; j < 4; ++j) acc[nt][j] = 0.f;
#pragma unroll
    for (int kk = 0; kk < 13; ++kk) {
      unsigned aF[4];
      const int ca = kk*2 + tg2;
      ldsm4(aBase + arow*T_AROWB + aphys(ca, arow)*16, aF);
      const int brow = kk*16 + bkoff;
      const unsigned bRow = bBase + brow*T_BROWB;
      const int ksw = brow & 7;
#pragma unroll
      for (int jp = 0; jp < 14; ++jp) {
        const int cH = 2*jp + tg2;
        const int ph = (cH & ~7) | ((cH & 7) ^ ksw);
        unsigned bb[4];
        ldsm4t(bRow + ph*16, bb);
        mma_bf16(acc[2*jp    ], aF, bb[0], bb[1]);
        mma_bf16(acc[2*jp + 1], aF, bb[2], bb[3]);
      }
    }
  };
  auto writebackA = [&]() {
    const int m0r = w*16 + g;
#pragma unroll
    for (int nt = 0; nt < 26; ++nt) {
      const int ph = aphys(nt, m0r);
      *(__nv_bfloat162*)(smt + m0r*T_AROWB + ph*16 + tig*4) =
          __nv_bfloat162(__float2bfloat16_rn(acc[nt][0]), __float2bfloat16_rn(acc[nt][1]));
      *(__nv_bfloat162*)(smt + (m0r + 8)*T_AROWB + ph*16 + tig*4) =
          __nv_bfloat162(__float2bfloat16_rn(acc[nt][2]), __float2bfloat16_rn(acc[nt][3]));
    }
  };

  // first mul: A = src[cnt-1], B = src[cnt-2]
  fillA(Sp(cnt - 1));
  fillB(Sp(cnt - 2));
  asm volatile("cp.async.commit_group;\n" ::: "memory");
  asm volatile("cp.async.wait_group 0;\n" ::: "memory");
  __syncthreads();
  mul();

  // chain remaining factors
  for (int j = cnt - 3; j >= 0; --j) {
    writebackA();                          // M -> warp-private A rows
    __syncthreads();                       // all warps done reading old B
    fillB(Sp(j));
    asm volatile("cp.async.commit_group;\n" ::: "memory");
    asm volatile("cp.async.wait_group 0;\n" ::: "memory");
    __syncthreads();
    mul();
  }

  // store
  const int r0g = row0 + w*16 + g;
  if (!final_lvl) {
    __nv_bfloat16* Cm = dstb + ((size_t)b*Lout + p)*MP2_;
#pragma unroll
    for (int nt = 0; nt < 28; ++nt) {
      const int col = nt*8 + 2*tig;
      *(__nv_bfloat162*)(Cm + (size_t)r0g*NP_ + col) =
          __nv_bfloat162(__float2bfloat16_rn(acc[nt][0]), __float2bfloat16_rn(acc[nt][1]));
      *(__nv_bfloat162*)(Cm + (size_t)(r0g + 8)*NP_ + col) =
          __nv_bfloat162(__float2bfloat16_rn(acc[nt][2]), __float2bfloat16_rn(acc[nt][3]));
    }
  } else {
    float* Cm = g_At + (size_t)b*MP2_;
#pragma unroll
    for (int nt = 0; nt < 28; ++nt) {
      const int col = nt*8 + 2*tig;
      *(float2*)(Cm + (size_t)r0g*NP_ + col)       = make_float2(acc[nt][0], acc[nt][1]);
      *(float2*)(Cm + (size_t)(r0g + 8)*NP_ + col) = make_float2(acc[nt][2], acc[nt][3]);
    }
  }
}

// =============================================================================
// Kernel D: per-row loss/acc, smem-staged coalesced loads. (unchanged)
// =============================================================================
#define SMEM_D_BYTES (N_*197*sizeof(float))

__global__ __launch_bounds__(224) void kD() {
  extern __shared__ float sd[];              // [196][197]
  __shared__ float sl[N_], sa[N_];
  const int b = blockIdx.x, tid = threadIdx.x;
  const float* At = g_At + (size_t)b*MP2_;
  for (int idx = tid; idx < N_*N_; idx += 224) {
    const int r = idx / N_, m = idx - r*N_;
    sd[r*197 + m] = At[(size_t)r*NP_ + m];
  }
  __syncthreads();
  if (tid < N_) {
    const float* row = sd + tid*197;
    float rs = 0.f, best = -1.f;
    int bi = 0;
    for (int m = 0; m < N_; ++m) {
      const float v = row[m];
      rs += v;
      if (v > best) { best = v; bi = m; }
    }
    const float diag = row[tid];
    sl[tid] = logf(rs + (float)N_ * EPS_) - logf(diag + EPS_);
    sa[tid] = (bi == tid) ? 1.f : 0.f;
  }
  __syncthreads();
  if (tid == 0) {
    float L = 0.f, A = 0.f;
    for (int i = 0; i < N_; ++i) { L += sl[i]; A += sa[i]; }
    g_partial[b]      = L;
    g_partial[B_ + b] = A;
  }
}

__global__ void kE(float* out, int out_size) {
  float L = 0.f, A = 0.f;
  for (int b = 0; b < B_; ++b) { L += g_partial[b]; A += g_partial[B_ + b]; }
  const float inv = 1.0f / (float)(B_ * N_);
  if (out_size > QSIZE)     out[QSIZE]     = L * inv;
  if (out_size > QSIZE + 1) out[QSIZE + 1] = A * inv;
}

// =============================================================================
extern "C" void kernel_launch(void* const* d_in, const int* in_sizes, int n_in,
                              void* d_out, int out_size) {
  const float* maps = (const float*)d_in[0];
  const float* W    = (const float*)d_in[1];
  const float* bias = (const float*)d_in[2];
  float* out = (float*)d_out;

  cudaFuncSetAttribute(kG, cudaFuncAttributeMaxDynamicSharedMemorySize, (int)SMEM_G_BYTES);
  cudaFuncSetAttribute(kQ, cudaFuncAttributeMaxDynamicSharedMemorySize, (int)SMEM_Q_BYTES);
  cudaFuncSetAttribute(kB, cudaFuncAttributeMaxDynamicSharedMemorySize, (int)SMEM_B2_BYTES);
  cudaFuncSetAttribute(kT, cudaFuncAttributeMaxDynamicSharedMemorySize, (int)SMEM_T_BYTES);
  cudaFuncSetAttribute(kD, cudaFuncAttributeMaxDynamicSharedMemorySize, (int)SMEM_D_BYTES);

  kW<<<256, 256>>>(W);
  kG<<<M_/64, 256, SMEM_G_BYTES>>>(maps, bias);
  kB<<<dim3(T_ - 1, B_), 448, SMEM_B2_BYTES>>>();
  kQ<<<dim3(T_, B_), 256, SMEM_Q_BYTES>>>(out);

  // quad-product tree: 38 -> 10 -> 3 -> 1
  kT<<<dim3(2, 10, B_), 224, SMEM_T_BYTES>>>(0, 38, 10, 4);
  kT<<<dim3(2,  3, B_), 224, SMEM_T_BYTES>>>(1, 10,  3, 4);
  kT<<<dim3(2,  1, B_), 224, SMEM_T_BYTES>>>(2,  3,  1, 3);

  kD<<<B_, 224, SMEM_D_BYTES>>>();
  kE<<<1, 1>>>(out, out_size);
}

// round 17
// speedup vs baseline: 1.0992x; 1.0828x over previous
#include <cuda_runtime.h>
#include <cuda_bf16.h>
#include <cuda_fp16.h>
#include <math.h>
#include <stdint.h>

#define B_ 16
#define N_ 196
#define C_ 512
#define T_ 20
#define D_ 128
#define S_ 38
#define NP_ 224                    // padded row/col stride for chain matrices
#define MP2_ (NP_*NP_)             // 50176 elems per padded matrix
#define M_ 62720                   // B*N*T rows of the head GEMM (=490*128)
#define QSIZE 8028160              // B*D*T*N
#define INV_TEMP (1.0f/0.07f)
#define EPS_ 1e-20f

// ---------------- scratch (static device globals; no allocation) ----------------
__device__ float g_qA[B_*T_*N_*D_];                                  // [b][t][n][d] fp32
__device__ __align__(256) __nv_bfloat16 g_qbf[B_*T_*N_*D_];          // bf16 copy of q
__device__ __align__(256) __half g_W1[C_*D_];                        // W fp16 [c][d]
__device__ __align__(256) __half g_W2[C_*D_];                        // W fp16 scaled-res
__device__ __align__(256) __nv_bfloat16 g_P [(size_t)B_*S_*MP2_ + 256];
__device__ __align__(256) __nv_bfloat16 g_b1[(size_t)B_*10*MP2_ + 256];
__device__ __align__(256) __nv_bfloat16 g_b2[(size_t)B_*3*MP2_ + 256];
__device__ float g_rowL[B_*N_];                                      // per-row -logp term
__device__ float g_rowA[B_*N_];                                      // per-row correct flag
__device__ float g_partial[2*B_];

// ---------------- mma / ldmatrix / cp.async helpers -------------------------
__device__ __forceinline__ void cpa16(void* dst_smem, const void* src) {
  unsigned d = (unsigned)__cvta_generic_to_shared(dst_smem);
  asm volatile("cp.async.cg.shared.global [%0], [%1], 16;\n" :: "r"(d), "l"(src));
}
__device__ __forceinline__ unsigned smem_u32p(const void* p) {
  return (unsigned)__cvta_generic_to_shared(p);
}
__device__ __forceinline__ void ldsm4(unsigned addr, unsigned* r) {
  asm volatile("ldmatrix.sync.aligned.m8n8.x4.shared.b16 {%0,%1,%2,%3}, [%4];\n"
               : "=r"(r[0]), "=r"(r[1]), "=r"(r[2]), "=r"(r[3]) : "r"(addr));
}
__device__ __forceinline__ void ldsm4t(unsigned addr, unsigned* r) {
  asm volatile("ldmatrix.sync.aligned.m8n8.x4.trans.shared.b16 {%0,%1,%2,%3}, [%4];\n"
               : "=r"(r[0]), "=r"(r[1]), "=r"(r[2]), "=r"(r[3]) : "r"(addr));
}
__device__ __forceinline__ void mma_bf16(float* d, const unsigned* a,
                                         unsigned b0, unsigned b1) {
  asm volatile(
      "mma.sync.aligned.m16n8k16.row.col.f32.bf16.bf16.f32 "
      "{%0,%1,%2,%3}, {%4,%5,%6,%7}, {%8,%9}, {%0,%1,%2,%3};\n"
      : "+f"(d[0]), "+f"(d[1]), "+f"(d[2]), "+f"(d[3])
      : "r"(a[0]), "r"(a[1]), "r"(a[2]), "r"(a[3]), "r"(b0), "r"(b1));
}
__device__ __forceinline__ void mma_f16(float* d, const unsigned* a,
                                        unsigned b0, unsigned b1) {
  asm volatile(
      "mma.sync.aligned.m16n8k16.row.col.f32.f16.f16.f32 "
      "{%0,%1,%2,%3}, {%4,%5,%6,%7}, {%8,%9}, {%0,%1,%2,%3};\n"
      : "+f"(d[0]), "+f"(d[1]), "+f"(d[2]), "+f"(d[3])
      : "r"(a[0]), "r"(a[1]), "r"(a[2]), "r"(a[3]), "r"(b0), "r"(b1));
}
__device__ __forceinline__ int aphys(int c, int r) {
  return (c < 24) ? ((c & ~7) | ((c & 7) ^ (r & 7))) : c;
}

// W split: W1/W2 fp16 planes ([c][d] layout, row-major in c)
__global__ void kW(const float* __restrict__ W) {
  const int i = blockIdx.x*256 + threadIdx.x;   // grid 256 x 256 = 65536
  const float x = W[i];
  const __half h = __float2half_rn(x);
  g_W1[i] = h;
  g_W2[i] = __float2half_rn(x + 255.0f*(x - __half2float(h)));
}

// =============================================================================
// Kernel G: FUSED pool + head GEMM (unchanged from R15).
// =============================================================================
#define GSTAGE 26624
#define SMEM_G_BYTES (2*GSTAGE)             // 53248

__global__ __launch_bounds__(256) void kG(const float* __restrict__ maps,
                                          const float* __restrict__ bias) {
  extern __shared__ char smg[];
  const int m0  = blockIdx.x * 64;
  const int tid = threadIdx.x;
  const int lane = tid & 31, w = tid >> 5;
  const int wm = w & 3, nh = w >> 2;
  const int g = lane >> 2, tig = lane & 3;
  const int tg1 = (lane >> 3) & 1, tg2 = (lane >> 4) & 1;

  const int c_loc  = (tid >> 1) & 31;
  const int m_base = ((tid >> 6) << 1) | (tid & 1);
  const float4* maps4 = reinterpret_cast<const float4*>(maps);
  const float4* pbase[8];
#pragma unroll
  for (int i = 0; i < 8; ++i) {
    const int m = m0 + m_base + 8*i;
    const int bn = m / 20, t = m - bn*20;
    pbase[i] = maps4 + (size_t)bn*10240 + (size_t)c_loc*20 + t;
  }
  float4 raw[8];

  auto ldraw = [&](int k0) {
    const int off = k0*20;
#pragma unroll
    for (int i = 0; i < 8; ++i) raw[i] = pbase[i][off];
  };
  auto stsA = [&](char* S) {
#pragma unroll
    for (int i = 0; i < 8; ++i) {
      const float v = (raw[i].x + raw[i].y + raw[i].z + raw[i].w) * 0.25f;
      const __half h1 = __float2half_rn(v);
      const __half h2 = __float2half_rn(v + 255.0f*(v - __half2float(h1)));
      const int ro = (m_base + 8*i)*80 + c_loc*2;
      *(__half*)(S + ro)        = h1;
      *(__half*)(S + 5120 + ro) = h2;
    }
  };
  auto fillB = [&](char* S, int k0) {
#pragma unroll
    for (int i = 0; i < 4; ++i) {
      const int idx = tid + i*256;
      const int r = idx >> 5, z = idx & 31;
      const int pl = z >> 4, c = z & 15;
      const int ph = (c & 8) | ((c & 7) ^ (r & 7));
      cpa16(S + 10240 + pl*8192 + r*256 + ph*16,
            (pl ? g_W2 : g_W1) + (size_t)(k0 + r)*D_ + c*8);
    }
    asm volatile("cp.async.commit_group;\n" ::: "memory");
  };

  float acc1[8][4], acc2[8][4];
#pragma unroll
  for (int nt = 0; nt < 8; ++nt)
#pragma unroll
    for (int j = 0; j < 4; ++j) { acc1[nt][j] = 0.f; acc2[nt][j] = 0.f; }

  ldraw(0);
  fillB(smg, 0);
  stsA(smg);

  for (int s = 0; s < 16; ++s) {
    asm volatile("cp.async.wait_group 0;\n" ::: "memory");
    __syncthreads();

    char* Snext = smg + ((s + 1) & 1)*GSTAGE;
    if (s + 1 < 16) {
      ldraw((s + 1)*32);
      fillB(Snext, (s + 1)*32);
    }

    const char* S = smg + (s & 1)*GSTAGE;
    const unsigned sBase = smem_u32p(S);
    const int arow = wm*16 + (lane & 7) + tg1*8;
#pragma unroll
    for (int ks = 0; ks < 2; ++ks) {
      unsigned a1[4], a2[4];
      {
        const unsigned ar = sBase + arow*80 + (ks*2 + tg2)*16;
        ldsm4(ar, a1);
        ldsm4(ar + 5120, a2);
      }
      const int brow = ks*16 + (lane & 7) + tg1*8;
#pragma unroll
      for (int jp = 0; jp < 4; ++jp) {
        const int c  = nh*8 + 2*jp + tg2;
        const int ph = (c & 8) | ((c & 7) ^ (brow & 7));
        const unsigned ba = sBase + 10240 + brow*256 + ph*16;
        unsigned b1[4], b2[4];
        ldsm4t(ba, b1);
        ldsm4t(ba + 8192, b2);
        mma_f16(acc1[2*jp    ], a1, b1[0], b1[1]);
        mma_f16(acc1[2*jp + 1], a1, b1[2], b1[3]);
        mma_f16(acc2[2*jp    ], a2, b2[0], b2[1]);
        mma_f16(acc2[2*jp + 1], a2, b2[2], b2[3]);
      }
    }
    if (s + 1 < 16) stsA(Snext);
  }
  __syncthreads();

  float* y       = (float*)smg;            // [64][129]
  float* partial = y + 64*129;             // [64][4]
  float* inorm   = partial + 256;          // [64]
  const float inv256 = 1.0f/256.0f;
  {
    const int row = wm*16 + g;
#pragma unroll
    for (int nt = 0; nt < 8; ++nt) {
      const int col = nh*64 + nt*8 + 2*tig;
      const float* p1 = acc1[nt];
      const float* p2 = acc2[nt];
      y[ row     *129 + col    ] = p1[0] + (p2[0] - p1[0])*inv256;
      y[ row     *129 + col + 1] = p1[1] + (p2[1] - p1[1])*inv256;
      y[(row + 8)*129 + col    ] = p1[2] + (p2[2] - p1[2])*inv256;
      y[(row + 8)*129 + col + 1] = p1[3] + (p2[3] - p1[3])*inv256;
    }
  }
  __syncthreads();
  {
    const int r = tid >> 2, hf = tid & 3;
    float ssum = 0.f;
#pragma unroll 8
    for (int d = hf*32; d < hf*32 + 32; ++d) {
      const float v = y[r*129 + d] + bias[d];
      y[r*129 + d] = v;
      ssum += v*v;
    }
    partial[r*4 + hf] = ssum;
  }
  __syncthreads();
  if (tid < 64)
    inorm[tid] = 1.0f / fmaxf(sqrtf(partial[tid*4] + partial[tid*4 + 1] +
                                    partial[tid*4 + 2] + partial[tid*4 + 3]), 1e-12f);
  __syncthreads();
  for (int i = tid; i < 64*128; i += 256) {
    const int rr = i >> 7, d = i & 127;
    const int m  = m0 + rr;
    const int bn = m / 20, t = m - bn*20;
    const int bq = bn / N_, n = bn - bq*N_;
    const float v = y[rr*129 + d] * inorm[rr];
    const size_t qi = ((size_t)(bq*T_ + t)*N_ + n)*D_ + d;
    g_qA[qi]  = v;
    g_qbf[qi] = __float2bfloat16_rn(v);
  }
}

// =============================================================================
// Kernel Q v2: transpose q to (B, d, T, N), split into 2 n-halves (640 CTAs).
// =============================================================================
#define SMEM_Q_BYTES (98*129*sizeof(float))

__global__ __launch_bounds__(256) void kQ(float* __restrict__ qout) {
  extern __shared__ float sq[];            // [98][129]
  const int t = blockIdx.x, b = blockIdx.y, z = blockIdx.z, tid = threadIdx.x;
  const int n0 = z * 98;
  const float* src = g_qA + ((size_t)(b*T_ + t)*N_ + n0)*D_;
  for (int i = tid; i < 98*D_; i += 256) {
    const int n = i >> 7, d = i & 127;
    sq[n*129 + d] = src[i];
  }
  __syncthreads();
  for (int i = tid; i < 98*D_; i += 256) {
    const int d = i / 98, n = i - d*98;
    qout[((size_t)(b*D_ + d)*T_ + t)*N_ + n0 + n] = sq[n*129 + d];
  }
}

// =============================================================================
// Kernel B: affinity + palindrome softmax on tensor cores. (unchanged R8)
// =============================================================================
#define KB_A_OFF 0
#define KB_B_OFF 57344                      // 224 rows x 256 B
#define KB_SM_OFF 114688
#define KB_SSTR 232                         // Sm bf16 col stride
#define SMEM_B2_BYTES (KB_SM_OFF + 224*KB_SSTR*2)   // 218624

__global__ __launch_bounds__(448, 1) void kB() {
  extern __shared__ char smb[];
  __shared__ float rinvA[224], cinvA[224];

  const int t = blockIdx.x, b = blockIdx.y, tid = threadIdx.x;
  const int lane = tid & 31, w = tid >> 5;
  const int g = lane >> 2, tig = lane & 3;

  {
    float4 z = make_float4(0.f, 0.f, 0.f, 0.f);
    ((float4*)(smb + KB_A_OFF + 196*256))[tid] = z;
    ((float4*)(smb + KB_B_OFF + 196*256))[tid] = z;
  }
  const __nv_bfloat16* Qa = g_qbf + ((size_t)(b*T_ + t    )*N_)*D_;
  const __nv_bfloat16* Qb = g_qbf + ((size_t)(b*T_ + t + 1)*N_)*D_;
  for (int idx = tid; idx < 196*16; idx += 448) {
    const int r = idx >> 4, c = idx & 15;
    const int ph = ((c & 7) ^ (r & 7)) | (c & 8);
    cpa16(smb + KB_A_OFF + r*256 + ph*16, Qa + (size_t)r*D_ + c*8);
    cpa16(smb + KB_B_OFF + r*256 + ph*16, Qb + (size_t)r*D_ + c*8);
  }
  asm volatile("cp.async.commit_group;\n" ::: "memory");
  asm volatile("cp.async.wait_group 0;\n" ::: "memory");
  __syncthreads();

  unsigned aF[8][4];
  {
    const int r = w*16 + (lane & 7) + ((lane >> 3) & 1)*8;
#pragma unroll
    for (int ks = 0; ks < 8; ++ks) {
      const int c  = 2*ks + ((lane >> 4) & 1);
      const int ph = ((c & 7) ^ (r & 7)) | (c & 8);
      ldsm4(smem_u32p(smb + KB_A_OFF) + r*256 + ph*16, aF[ks]);
    }
  }

  const unsigned bBase = smem_u32p(smb + KB_B_OFF);
  __nv_bfloat16* Sm = (__nv_bfloat16*)(smb + KB_SM_OFF);
  const int m0r = w*16 + g;
  float rsum0 = 0.f, rsum1 = 0.f;

  const int brlo = (lane & 7) + ((lane >> 4) & 1)*8;
  const int bchi = (lane >> 3) & 1;

  for (int ch = 0; ch < 7; ++ch) {
    float acc[4][4];
#pragma unroll
    for (int nt = 0; nt < 4; ++nt)
#pragma unroll
      for (int j = 0; j < 4; ++j) acc[nt][j] = 0.f;

#pragma unroll
    for (int ks = 0; ks < 8; ++ks) {
#pragma unroll
      for (int half = 0; half < 2; ++half) {
        const int r  = ch*32 + half*16 + brlo;
        const int c  = 2*ks + bchi;
        const int ph = ((c & 7) ^ (r & 7)) | (c & 8);
        unsigned bf[4];
        ldsm4(bBase + r*256 + ph*16, bf);
        mma_bf16(acc[half*2    ], aF[ks], bf[0], bf[1]);
        mma_bf16(acc[half*2 + 1], aF[ks], bf[2], bf[3]);
      }
    }
#pragma unroll
    for (int nt = 0; nt < 4; ++nt) {
      const int col = ch*32 + nt*8 + 2*tig;
      const float e0 = __expf(acc[nt][0]*INV_TEMP);
      const float e1 = __expf(acc[nt][1]*INV_TEMP);
      const float e2 = __expf(acc[nt][2]*INV_TEMP);
      const float e3 = __expf(acc[nt][3]*INV_TEMP);
      if (col     < N_) { rsum0 += e0; rsum1 += e2; }
      if (col + 1 < N_) { rsum0 += e1; rsum1 += e3; }
      *(__nv_bfloat162*)(Sm + (size_t)m0r*KB_SSTR + col) =
          __nv_bfloat162(__float2bfloat16_rn(e0), __float2bfloat16_rn(e1));
      *(__nv_bfloat162*)(Sm + (size_t)(m0r + 8)*KB_SSTR + col) =
          __nv_bfloat162(__float2bfloat16_rn(e2), __float2bfloat16_rn(e3));
    }
  }
  rsum0 += __shfl_xor_sync(0xffffffffu, rsum0, 1);
  rsum0 += __shfl_xor_sync(0xffffffffu, rsum0, 2);
  rsum1 += __shfl_xor_sync(0xffffffffu, rsum1, 1);
  rsum1 += __shfl_xor_sync(0xffffffffu, rsum1, 2);
  if (tig == 0) {
    rinvA[m0r]     = 1.0f / rsum0;
    rinvA[m0r + 8] = 1.0f / rsum1;
  }
  __syncthreads();
  {
    const int col = tid >> 1, r0 = (tid & 1)*98;
    float cs = 0.f;
    for (int r = r0; r < r0 + 98; ++r)
      cs += __bfloat162float(Sm[(size_t)r*KB_SSTR + col]);
    cs += __shfl_xor_sync(0xffffffffu, cs, 1);
    if ((tid & 1) == 0) cinvA[col] = 1.0f / cs;
  }
  __syncthreads();
  __nv_bfloat16* Pf = g_P + (size_t)(b*S_ + t       )*MP2_;
  __nv_bfloat16* Pb = g_P + (size_t)(b*S_ + (37 - t))*MP2_;
  for (int idx = tid; idx < 224*112; idx += 448) {
    const int r = idx / 112, m2 = (idx - r*112)*2;
    float f0 = 0.f, f1 = 0.f, p0 = 0.f, p1 = 0.f;
    if (r < N_) {
      const float ri = rinvA[r], ci = cinvA[r];
      if (m2 < N_) {
        f0 = __bfloat162float(Sm[(size_t)r*KB_SSTR + m2]) * ri;
        p0 = __bfloat162float(Sm[(size_t)m2*KB_SSTR + r]) * ci;
      }
      if (m2 + 1 < N_) {
        f1 = __bfloat162float(Sm[(size_t)r*KB_SSTR + m2 + 1]) * ri;
        p1 = __bfloat162float(Sm[(size_t)(m2 + 1)*KB_SSTR + r]) * ci;
      }
    }
    *(__nv_bfloat162*)(Pf + (size_t)r*NP_ + m2) =
        __nv_bfloat162(__float2bfloat16_rn(f0), __float2bfloat16_rn(f1));
    *(__nv_bfloat162*)(Pb + (size_t)r*NP_ + m2) =
        __nv_bfloat162(__float2bfloat16_rn(p0), __float2bfloat16_rn(p1));
  }
}

// =============================================================================
// Kernel T v3: fused GROUP-product tree level, B fill pipelined in halves.
// Levels: 38 -> 10 -> 3 -> 1. Final level computes per-row loss stats directly
// from fp32 accumulators (no g_At round trip).
// =============================================================================
#define T_AROWB 416
#define T_ABYTES (112*T_AROWB)              // 46592
#define T_BROWB 512
#define T_BBYTES (208*T_BROWB)              // 106496
#define SMEM_T_BYTES (T_ABYTES + T_BBYTES)  // 153088

__global__ __launch_bounds__(224) void kT(int level, int Lin, int Lout, int group) {
  extern __shared__ char smt[];

  const __nv_bfloat16* src; __nv_bfloat16* dstb;
  switch (level) {
    case 0:  src = g_P;  dstb = g_b1; break;
    case 1:  src = g_b1; dstb = g_b2; break;
    default: src = g_b2; dstb = 0;   break;   // final level -> loss stats
  }
  const bool final_lvl = (level >= 2);

  const int tile = blockIdx.x;        // 0..1 row halves
  const int p    = blockIdx.y;
  const int b    = blockIdx.z;
  const int tid  = threadIdx.x;
  const int base = group*p;
  int cnt = Lin - base; if (cnt > group) cnt = group;
  const int row0 = tile * 112;

  const int lane = tid & 31, w = tid >> 5;
  const int tg1 = (lane >> 3) & 1, tg2 = (lane >> 4) & 1;
  const int g = lane >> 2, tig = lane & 3;
  const int arow  = w*16 + (lane & 7) + tg1*8;
  const int bkoff = (lane & 7) + tg1*8;
  const unsigned aBase = smem_u32p(smt);
  const unsigned bBase = smem_u32p(smt + T_ABYTES);

  auto Sp = [&](int j) { return src + ((size_t)b*Lin + base + j)*MP2_; };

  auto fillA = [&](const __nv_bfloat16* Ms) {
    const char* Am = (const char*)Ms;
    const int r = tid >> 1, cb = tid & 1;
#pragma unroll
    for (int i = 0; i < 13; ++i) {
      const int c = cb + 2*i;
      cpa16(smt + r*T_AROWB + aphys(c, r)*16, Am + (size_t)(row0 + r)*448 + c*16);
    }
  };
  auto fillBhalf = [&](const __nv_bfloat16* Ms, int rlo, int rhi) {
    const char* Bm = (const char*)Ms;
    const int tot = (rhi - rlo)*28;
    for (int idx = tid; idx < tot; idx += 224) {
      const int r = rlo + idx / 28, c = idx - (idx/28)*28;
      const int ph = (c & ~7) | ((c & 7) ^ (r & 7));
      cpa16(smt + T_ABYTES + r*T_BROWB + ph*16, Bm + (size_t)r*448 + c*16);
    }
    asm volatile("cp.async.commit_group;\n" ::: "memory");
  };

  float acc[28][4];
  auto mulRange = [&](int k0, int k1) {
#pragma unroll 2
    for (int kk = k0; kk < k1; ++kk) {
      unsigned aF[4];
      const int ca = kk*2 + tg2;
      ldsm4(aBase + arow*T_AROWB + aphys(ca, arow)*16, aF);
      const int brow = kk*16 + bkoff;
      const unsigned bRow = bBase + brow*T_BROWB;
      const int ksw = brow & 7;
#pragma unroll
      for (int jp = 0; jp < 14; ++jp) {
        const int cH = 2*jp + tg2;
        const int ph = (cH & ~7) | ((cH & 7) ^ ksw);
        unsigned bb[4];
        ldsm4t(bRow + ph*16, bb);
        mma_bf16(acc[2*jp    ], aF, bb[0], bb[1]);
        mma_bf16(acc[2*jp + 1], aF, bb[2], bb[3]);
      }
    }
  };
  auto zeroAcc = [&]() {
#pragma unroll
    for (int nt = 0; nt < 28; ++nt)
#pragma unroll
      for (int j = 0; j < 4; ++j) acc[nt][j] = 0.f;
  };
  auto writebackA = [&]() {
    const int m0r = w*16 + g;
#pragma unroll
    for (int nt = 0; nt < 26; ++nt) {
      const int ph = aphys(nt, m0r);
      *(__nv_bfloat162*)(smt + m0r*T_AROWB + ph*16 + tig*4) =
          __nv_bfloat162(__float2bfloat16_rn(acc[nt][0]), __float2bfloat16_rn(acc[nt][1]));
      *(__nv_bfloat162*)(smt + (m0r + 8)*T_AROWB + ph*16 + tig*4) =
          __nv_bfloat162(__float2bfloat16_rn(acc[nt][2]), __float2bfloat16_rn(acc[nt][3]));
    }
  };

  // first mul: A = src[cnt-1], B = src[cnt-2], B fill split lo/hi
  fillA(Sp(cnt - 1));
  fillBhalf(Sp(cnt - 2), 0, 112);      // group: A + B_lo
  fillBhalf(Sp(cnt - 2), 112, 208);    // group: B_hi
  asm volatile("cp.async.wait_group 1;\n" ::: "memory");
  __syncthreads();
  zeroAcc();
  mulRange(0, 7);
  asm volatile("cp.async.wait_group 0;\n" ::: "memory");
  __syncthreads();
  mulRange(7, 13);

  // chain remaining factors
  for (int j = cnt - 3; j >= 0; --j) {
    writebackA();
    __syncthreads();                   // all warps done with old B
    fillBhalf(Sp(j), 0, 112);
    fillBhalf(Sp(j), 112, 208);
    asm volatile("cp.async.wait_group 1;\n" ::: "memory");
    __syncthreads();
    zeroAcc();
    mulRange(0, 7);
    asm volatile("cp.async.wait_group 0;\n" ::: "memory");
    __syncthreads();
    mulRange(7, 13);
  }

  // store / loss
  const int r0g = row0 + w*16 + g;
  if (!final_lvl) {
    __nv_bfloat16* Cm = dstb + ((size_t)b*Lout + p)*MP2_;
#pragma unroll
    for (int nt = 0; nt < 28; ++nt) {
      const int col = nt*8 + 2*tig;
      *(__nv_bfloat162*)(Cm + (size_t)r0g*NP_ + col) =
          __nv_bfloat162(__float2bfloat16_rn(acc[nt][0]), __float2bfloat16_rn(acc[nt][1]));
      *(__nv_bfloat162*)(Cm + (size_t)(r0g + 8)*NP_ + col) =
          __nv_bfloat162(__float2bfloat16_rn(acc[nt][2]), __float2bfloat16_rn(acc[nt][3]));
    }
  } else {
    // per-row loss stats from registers: rows r0g, r0g+8
#pragma unroll
    for (int half = 0; half < 2; ++half) {
      const int row = r0g + half*8;
      float sum = 0.f, dg = 0.f, mx = -1.f;
      int mi = 0;
#pragma unroll
      for (int nt = 0; nt < 28; ++nt) {
#pragma unroll
        for (int jj = 0; jj < 2; ++jj) {
          const int col = nt*8 + 2*tig + jj;
          const float v = acc[nt][2*half + jj];
          if (col < N_) {
            sum += v;
            if (v > mx) { mx = v; mi = col; }
            if (col == row) dg = v;
          }
        }
      }
      // reduce over tig (lanes xor 1, xor 2)
#pragma unroll
      for (int m = 1; m <= 2; m <<= 1) {
        sum += __shfl_xor_sync(0xffffffffu, sum, m);
        dg  += __shfl_xor_sync(0xffffffffu, dg,  m);
        const float omx = __shfl_xor_sync(0xffffffffu, mx, m);
        const int   omi = __shfl_xor_sync(0xffffffffu, mi, m);
        if (omx > mx || (omx == mx && omi < mi)) { mx = omx; mi = omi; }
      }
      if (tig == 0 && row < N_) {
        g_rowL[b*N_ + row] = logf(sum + (float)N_*EPS_) - logf(dg + EPS_);
        g_rowA[b*N_ + row] = (mi == row) ? 1.f : 0.f;
      }
    }
  }
}

// =============================================================================
// Kernel D: tiny per-b reduction of row stats.
// =============================================================================
__global__ __launch_bounds__(224) void kD() {
  __shared__ float sl[N_], sa[N_];
  const int b = blockIdx.x, tid = threadIdx.x;
  if (tid < N_) {
    sl[tid] = g_rowL[b*N_ + tid];
    sa[tid] = g_rowA[b*N_ + tid];
  }
  __syncthreads();
  if (tid == 0) {
    float L = 0.f, A = 0.f;
    for (int i = 0; i < N_; ++i) { L += sl[i]; A += sa[i]; }
    g_partial[b]      = L;
    g_partial[B_ + b] = A;
  }
}

__global__ void kE(float* out, int out_size) {
  float L = 0.f, A = 0.f;
  for (int b = 0; b < B_; ++b) { L += g_partial[b]; A += g_partial[B_ + b]; }
  const float inv = 1.0f / (float)(B_ * N_);
  if (out_size > QSIZE)     out[QSIZE]     = L * inv;
  if (out_size > QSIZE + 1) out[QSIZE + 1] = A * inv;
}

// =============================================================================
extern "C" void kernel_launch(void* const* d_in, const int* in_sizes, int n_in,
                              void* d_out, int out_size) {
  const float* maps = (const float*)d_in[0];
  const float* W    = (const float*)d_in[1];
  const float* bias = (const float*)d_in[2];
  float* out = (float*)d_out;

  cudaFuncSetAttribute(kG, cudaFuncAttributeMaxDynamicSharedMemorySize, (int)SMEM_G_BYTES);
  cudaFuncSetAttribute(kQ, cudaFuncAttributeMaxDynamicSharedMemorySize, (int)SMEM_Q_BYTES);
  cudaFuncSetAttribute(kB, cudaFuncAttributeMaxDynamicSharedMemorySize, (int)SMEM_B2_BYTES);
  cudaFuncSetAttribute(kT, cudaFuncAttributeMaxDynamicSharedMemorySize, (int)SMEM_T_BYTES);

  kW<<<256, 256>>>(W);
  kG<<<M_/64, 256, SMEM_G_BYTES>>>(maps, bias);
  kB<<<dim3(T_ - 1, B_), 448, SMEM_B2_BYTES>>>();
  kQ<<<dim3(T_, B_, 2), 256, SMEM_Q_BYTES>>>(out);

  // quad-product tree: 38 -> 10 -> 3 -> 1
  kT<<<dim3(2, 10, B_), 224, SMEM_T_BYTES>>>(0, 38, 10, 4);
  kT<<<dim3(2,  3, B_), 224, SMEM_T_BYTES>>>(1, 10,  3, 4);
  kT<<<dim3(2,  1, B_), 224, SMEM_T_BYTES>>>(2,  3,  1, 3);

  kD<<<B_, 224>>>();
  kE<<<1, 1>>>(out, out_size);
}